// round 9
// baseline (speedup 1.0000x reference)
#include <cuda_runtime.h>
#include <cstddef>
#include <cstdint>

#define BB   8
#define NF   64
#define FIN  192
#define FH   128
#define LATD 512
#define PT   61824
#define P0   16384   // 128*128

// ---------------- scratch (device globals; no allocation) ----------------
__device__ float g_out [BB*NF *P0];
__device__ float g_h1  [BB*FH *P0];
__device__ float g_h2  [BB*FH *P0];
__device__ float g_full[BB*NF *P0];
__device__ float g_dyn [BB*PT];
__device__ float g_wAT [BB*FIN*FH];   // [192][128] per sample (w_in^T)
__device__ float g_wMT [BB*FH*FH];    // [128][128] per sample (w_mid^T)
__device__ float g_wCDT[BB*320*NF];   // [320][64]: rows 0..127 w_out^T, 128..319 w_sk^T
__device__ float g_bA  [BB*FH];
__device__ float g_bM  [BB*FH];
__device__ float g_bCD [BB*NF];
__device__ float g_hvec[BB*NF];
__device__ float g_wRB [2*NF*NF];     // transposed inrb_w0, inrb_w1 (shared across batch)

__device__ __forceinline__ float lrelu(float x){ return x > 0.0f ? x : 0.2f*x; }
__device__ __forceinline__ float4 lrelu4(float4 v){
    return make_float4(lrelu(v.x), lrelu(v.y), lrelu(v.z), lrelu(v.w));
}
__device__ __forceinline__ void fma2(unsigned long long &d, unsigned long long a, unsigned long long b) {
    asm("fma.rn.f32x2 %0, %1, %2, %0;" : "+l"(d) : "l"(a), "l"(b));
}
__device__ __forceinline__ float2 unpack2(unsigned long long v) {
    float2 r; asm("mov.b64 {%0,%1}, %2;" : "=f"(r.x), "=f"(r.y) : "l"(v)); return r;
}
__device__ __forceinline__ unsigned long long pack2(float lo, float hi) {
    unsigned long long r; asm("mov.b64 %0, {%1,%2};" : "=l"(r) : "f"(lo), "f"(hi)); return r;
}

// sobel-on-the-fly: compute 4 consecutive values of channel-type `type` (0=id,
// 1=d/dx, 2=d/dy) at pixels m..m+3 of `src` (one image of H x H, m 4-aligned,
// m < P). Math identical to the former k_sobel4 kernel.
__device__ __forceinline__ float4 sobel_load4(const float* __restrict__ src,
                                              int m, int H, int lgH, int type)
{
    if (type == 0) return *(const float4*)(src + m);
    const int y  = m >> lgH, x0 = m & (H-1);
    float am[6], acv[6], apv[6];
    {
        float4 v = *(const float4*)&src[m];
        acv[0] = (x0 > 0)   ? src[m-1] : 0.f;
        acv[1] = v.x; acv[2] = v.y; acv[3] = v.z; acv[4] = v.w;
        acv[5] = (x0+4 < H) ? src[m+4] : 0.f;
    }
    if (y > 0) {
        int base = (y-1) << lgH;
        float4 v = *(const float4*)&src[base + x0];
        am[0] = (x0 > 0)   ? src[base+x0-1] : 0.f;
        am[1] = v.x; am[2] = v.y; am[3] = v.z; am[4] = v.w;
        am[5] = (x0+4 < H) ? src[base+x0+4] : 0.f;
    } else { am[0]=am[1]=am[2]=am[3]=am[4]=am[5]=0.f; }
    if (y < H-1) {
        int base = (y+1) << lgH;
        float4 v = *(const float4*)&src[base + x0];
        apv[0] = (x0 > 0)   ? src[base+x0-1] : 0.f;
        apv[1] = v.x; apv[2] = v.y; apv[3] = v.z; apv[4] = v.w;
        apv[5] = (x0+4 < H) ? src[base+x0+4] : 0.f;
    } else { apv[0]=apv[1]=apv[2]=apv[3]=apv[4]=apv[5]=0.f; }

    float s[4];
    #pragma unroll
    for (int i = 0; i < 4; ++i) {
        float m00 = am[i], m01 = am[i+1], m02 = am[i+2];
        float m10 = acv[i],               m12 = acv[i+2];
        float m20 = apv[i], m21 = apv[i+1], m22 = apv[i+2];
        if (type == 1)
            s[i] = (m00 - m02 + 2.f*(m10 - m12) + m20 - m22) * 0.125f;
        else
            s[i] = (m00 + 2.f*m01 + m02 - m20 - 2.f*m21 - m22) * 0.125f;
    }
    return make_float4(s[0], s[1], s[2], s[3]);
}

// ---------------- input 1x1 conv (3 -> 64): y -> g_full ----------------
__global__ void k_inconv(const float* __restrict__ x, const float* __restrict__ in_w,
                         const float* __restrict__ in_b)
{
    const int idx = blockIdx.x*256 + threadIdx.x;   // BB*NF*P0/4 = 2^21
    const int p4 = (idx & 4095) << 2;
    const int o  = (idx >> 12) & 63;
    const int b  = idx >> 18;
    const float w0 = in_w[o*3+0], w1 = in_w[o*3+1], w2 = in_w[o*3+2], bv = in_b[o];
    const float* xp = x + (size_t)(b*3)*P0 + p4;
    float4 a = *(const float4*)xp;
    float4 c = *(const float4*)(xp + P0);
    float4 d = *(const float4*)(xp + 2*P0);
    float4 r;
    r.x = bv + w0*a.x + w1*c.x + w2*d.x;
    r.y = bv + w0*a.y + w1*c.y + w2*d.y;
    r.z = bv + w0*a.z + w1*c.z + w2*d.z;
    r.w = bv + w0*a.w + w1*c.w + w2*d.w;
    *(float4*)&g_full[(size_t)(b*NF+o)*P0 + p4] = r;
}

// ---------------- transpose static resblock weights ----------------
__global__ void k_trw(const float* __restrict__ w0, const float* __restrict__ w1)
{
    const int i = blockIdx.x*256 + threadIdx.x;   // 8192
    if (i < 4096) { int k = i >> 6, o = i & 63; g_wRB[i] = w0[o*64 + k]; }
    else { int j = i - 4096; int k = j >> 6, o = j & 63; g_wRB[i] = w1[o*64 + k]; }
}

// ---------------- hypernet: dyn = inj_lat @ hyp_w + hyp_b (float4) ----------------
__global__ void k_hyper(const float* __restrict__ inj, const float* __restrict__ hw,
                        const float* __restrict__ hb)
{
    __shared__ float s_inj[BB*LATD];
    const int tid = threadIdx.x;  // 128
    for (int e = tid; e < BB*LATD; e += 128) s_inj[e] = inj[e];
    __syncthreads();
    const int j4 = (blockIdx.x*128 + tid) * 4;
    if (j4 >= PT) return;
    float4 acc[BB];
    #pragma unroll
    for (int b = 0; b < BB; ++b) acc[b] = make_float4(0.f,0.f,0.f,0.f);
    for (int k = 0; k < LATD; ++k) {
        float4 w = *(const float4*)&hw[(size_t)k*PT + j4];
        #pragma unroll
        for (int b = 0; b < BB; ++b) {
            float s = s_inj[b*LATD+k];
            acc[b].x += s*w.x; acc[b].y += s*w.y;
            acc[b].z += s*w.z; acc[b].w += s*w.w;
        }
    }
    float4 bb = *(const float4*)&hb[j4];
    #pragma unroll
    for (int b = 0; b < BB; ++b) {
        float4 r = make_float4(acc[b].x+bb.x, acc[b].y+bb.y, acc[b].z+bb.z, acc[b].w+bb.w);
        *(float4*)&g_dyn[(size_t)b*PT + j4] = r;
    }
}

// ---------------- transpose dyn params into GEMM-friendly layout ----------------
__global__ void k_tr()
{
    const int b = blockIdx.y;
    int i = blockIdx.x*256 + threadIdx.x;
    const float* d = g_dyn + (size_t)b*PT;
    if (i < FIN*FH) { int k = i/FH, o = i%FH; g_wAT[(size_t)b*FIN*FH + i] = d[o*FIN + k]; return; }
    i -= FIN*FH;
    if (i < FH*FH)  { int k = i/FH, o = i%FH; g_wMT[(size_t)b*FH*FH + i] = d[24704 + o*FH + k]; return; }
    i -= FH*FH;
    if (i < 320*NF) { int k = i/NF, o = i%NF;
        g_wCDT[(size_t)b*320*NF + i] = (k < FH) ? d[41216 + o*FH + k]
                                                : d[49472 + o*FIN + (k-FH)];
        return; }
    i -= 320*NF;
    if (i < FH) { g_bA[b*FH+i] = d[24576+i]; return; }
    i -= FH;
    if (i < FH) { g_bM[b*FH+i] = d[41088+i]; return; }
    i -= FH;
    if (i < NF) { g_bCD[b*NF+i] = d[49408+i] + d[61760+i]; return; }
}

// ---------------- SGEMM: C[n][p] = sum_k A[k][p] * Wt[k][n] (+epilogue) ----------
// 256 threads, per-thread 8M x 8N via fma.rn.f32x2 (M packed in pairs).
// Plain W in smem; (w,w) duplication in registers (ALU pipe) — keeps the smem
// crossbar at 4 LDS.128/thread/kc, balanced with the FMA pipe.
// EPI 0: C = lrelu(v+bias)
// EPI 1: C = O + clip(*leak)*(v+bias)
// EPI 2: C = O + 0.1*(v+bias), dual-store to C2
// ACT : apply lrelu to A elements when staging to smem
// SOBEL 0: plain A1/A2.  1: A1 is virtual sin_sobel(A1-image[NF ch]), K1=192.
//       2: A2 is virtual sin_sobel(A2-image[NF ch]), K2=192.
template<int BM, int BN, int EPI, bool ACT, int SOBEL>
__global__ void __launch_bounds__(256, 1) k_gemm(
    const float* __restrict__ A1, int K1, long long sA1,
    const float* __restrict__ A2, int K2, long long sA2,
    const float* __restrict__ Wt, int ldw, long long sW,
    const float* __restrict__ bias, int sBias,
    float* __restrict__ C, long long sC,
    float* __restrict__ C2,
    const float* __restrict__ O, const float* __restrict__ leak_ptr,
    int P, int H, int lgH)
{
    constexpr int BK  = 16;
    constexpr int TMC = BM/8;              // threads along M
    constexpr int NA  = BK*BM/1024;        // float4 A loads per thread
    constexpr int NW  = (BK*BN >= 1024) ? BK*BN/1024 : 1;  // float4 W loads per thread

    __shared__ float As[2][BK][BM];
    __shared__ float Ws[2][BK][BN];

    const int b  = blockIdx.y;
    const int m0 = blockIdx.x * BM;
    A1 += (size_t)b * sA1;
    if (A2) A2 += (size_t)b * sA2;
    Wt   += (size_t)b * sW;
    bias += (size_t)b * sBias;

    const int tid = threadIdx.x;
    const int tm = tid % TMC;
    const int tn = tid / TMC;

    unsigned long long acc[2][2][4][2];
    #pragma unroll
    for (int af = 0; af < 2; ++af)
        #pragma unroll
        for (int wf = 0; wf < 2; ++wf)
            #pragma unroll
            for (int j = 0; j < 4; ++j) { acc[af][wf][j][0] = 0ULL; acc[af][wf][j][1] = 0ULL; }

    const int K = K1 + K2;
    const int T = K / BK;

    float4 pa[NA], pw[NW];
    auto prefetch = [&](int k0) {
        #pragma unroll
        for (int l = 0; l < NA; ++l) {
            int f  = tid + l*256;
            int kc = f / (BM/4);
            int mv = (f % (BM/4)) * 4;
            int kk = k0 + kc;
            int m  = m0 + mv;
            float4 v;
            if (m >= P) {
                v = make_float4(0.f,0.f,0.f,0.f);
            } else if (SOBEL == 1) {
                int type = kk >> 6, c = kk & 63;
                v = sobel_load4(A1 + (size_t)c*P, m, H, lgH, type);
            } else if (SOBEL == 2 && kk >= K1) {
                int ks = kk - K1;
                int type = ks >> 6, c = ks & 63;
                v = sobel_load4(A2 + (size_t)c*P, m, H, lgH, type);
            } else {
                const float* src = (kk < K1) ? (A1 + (size_t)kk*P) : (A2 + (size_t)(kk-K1)*P);
                v = *(const float4*)(src + m);
            }
            pa[l] = v;
        }
        #pragma unroll
        for (int l = 0; l < NW; ++l) {
            int f  = tid + l*256;
            int kc = f / (BN/4);
            int nv = (f % (BN/4)) * 4;
            pw[l] = *(const float4*)(Wt + (size_t)(k0+kc)*ldw + nv);
        }
    };
    auto store_tile = [&](int nb) {
        #pragma unroll
        for (int l = 0; l < NA; ++l) {
            int f  = tid + l*256;
            int kc = f / (BM/4);
            int mv = (f % (BM/4)) * 4;
            *(float4*)&As[nb][kc][mv] = ACT ? lrelu4(pa[l]) : pa[l];
        }
        #pragma unroll
        for (int l = 0; l < NW; ++l) {
            int f  = tid + l*256;
            int kc = f / (BN/4);
            int nv = (f % (BN/4)) * 4;
            *(float4*)&Ws[nb][kc][nv] = pw[l];
        }
    };

    prefetch(0);
    store_tile(0);
    __syncthreads();

    for (int t = 0; t < T; ++t) {
        const int buf = t & 1;
        if (t + 1 < T) prefetch((t + 1) * BK);
        #pragma unroll
        for (int kc = 0; kc < BK; ++kc) {
            ulonglong2 aA = *(const ulonglong2*)&As[buf][kc][tm*4];
            ulonglong2 aB = *(const ulonglong2*)&As[buf][kc][BM/2 + tm*4];
            float4 wa = *(const float4*)&Ws[buf][kc][tn*4];
            float4 wb = *(const float4*)&Ws[buf][kc][BN/2 + tn*4];
            unsigned long long wd[2][4];
            wd[0][0] = pack2(wa.x, wa.x); wd[0][1] = pack2(wa.y, wa.y);
            wd[0][2] = pack2(wa.z, wa.z); wd[0][3] = pack2(wa.w, wa.w);
            wd[1][0] = pack2(wb.x, wb.x); wd[1][1] = pack2(wb.y, wb.y);
            wd[1][2] = pack2(wb.z, wb.z); wd[1][3] = pack2(wb.w, wb.w);
            #pragma unroll
            for (int wf = 0; wf < 2; ++wf)
                #pragma unroll
                for (int j = 0; j < 4; ++j) {
                    fma2(acc[0][wf][j][0], wd[wf][j], aA.x);
                    fma2(acc[0][wf][j][1], wd[wf][j], aA.y);
                    fma2(acc[1][wf][j][0], wd[wf][j], aB.x);
                    fma2(acc[1][wf][j][1], wd[wf][j], aB.y);
                }
        }
        if (t + 1 < T) store_tile(buf ^ 1);
        __syncthreads();
    }

    float lk = 0.1f;
    if (EPI == 1) { lk = *leak_ptr; lk = fminf(fmaxf(lk, 0.001f), 1000.f); }
    #pragma unroll
    for (int af = 0; af < 2; ++af) {
        const int m = m0 + (af ? BM/2 : 0) + tm*4;
        if (m >= P) continue;
        #pragma unroll
        for (int wf = 0; wf < 2; ++wf) {
            #pragma unroll
            for (int j = 0; j < 4; ++j) {
                const int n = (wf ? BN/2 : 0) + tn*4 + j;
                const float bv = bias[n];
                float2 p0 = unpack2(acc[af][wf][j][0]);
                float2 p1 = unpack2(acc[af][wf][j][1]);
                float4 v = make_float4(p0.x+bv, p0.y+bv, p1.x+bv, p1.y+bv);
                const size_t off = (size_t)b*sC + (size_t)n*P + m;
                if (EPI == 0) {
                    *(float4*)&C[off] = lrelu4(v);
                } else {
                    float4 o = *(const float4*)&O[off];
                    v.x = o.x + lk*v.x; v.y = o.y + lk*v.y;
                    v.z = o.z + lk*v.z; v.w = o.w + lk*v.w;
                    *(float4*)&C[off] = v;
                    if (EPI == 2) *(float4*)&C2[off] = v;
                }
            }
        }
    }
}

// ---------------- gauss 3x3 (zero pad) + 2x2 mean, writes g_out + emb ----------------
__global__ void k_down(int H, int lgH, float* __restrict__ emb)
{
    const int Hn = H >> 1, Pn = Hn*Hn;
    const int lgHn = lgH - 1;
    const int idx = blockIdx.x*256 + threadIdx.x;
    if (idx >= BB*NF*Pn) return;
    const int p = idx & (Pn-1);
    const int c = (idx >> (2*lgHn)) & (NF-1);
    const int b = idx >> (2*lgHn + 6);
    const int oy = p >> lgHn, ox = p & (Hn-1);
    const float* src = g_full + (size_t)(b*NF+c)*H*H;
    const float G0 = 0.27406861906119695f;
    const float G1 = 0.72593138093880305f;
    const float u4[4] = {G0, G1, G1, G0};
    float acc = 0.f;
    #pragma unroll
    for (int r = 0; r < 4; ++r) {
        int yy = 2*oy + r - 1;
        if (yy < 0 || yy >= H) continue;
        float rowacc = 0.f;
        #pragma unroll
        for (int cc = 0; cc < 4; ++cc) {
            int xx = 2*ox + cc - 1;
            if (xx < 0 || xx >= H) continue;
            rowacc += u4[cc]*src[(yy<<lgH)+xx];
        }
        acc += u4[r]*rowacc;
    }
    acc *= 0.25f;
    const size_t o = (size_t)(b*NF+c)*Pn + p;
    g_out[o] = acc;
    emb[o]   = acc;
}

// ---------------- tail res_block at 2x2 + spatial mean -> g_hvec ----------------
__global__ void k_tail(const float* __restrict__ w0, const float* __restrict__ b0,
                       const float* __restrict__ w1, const float* __restrict__ b1)
{
    __shared__ float s_w0[NF*NF], s_w1[NF*NF], s_a[NF*4];
    const int o = threadIdx.x, b = blockIdx.x;
    for (int e = o; e < NF*NF; e += 64) {
        int r = e >> 6, i = e & 63;
        s_w0[(r<<6) | ((i + r) & 63)] = w0[e];
        s_w1[(r<<6) | ((i + r) & 63)] = w1[e];
    }
    const float bb0 = b0[o], bb1 = b1[o];
    __syncthreads();
    float v[4];
    #pragma unroll
    for (int py = 0; py < 4; ++py) v[py] = g_out[(size_t)(b*NF+o)*4 + py];
    *(float4*)&s_a[o*4] = make_float4(lrelu(v[0]),lrelu(v[1]),lrelu(v[2]),lrelu(v[3]));
    __syncthreads();
    float t[4] = {bb0,bb0,bb0,bb0};
    #pragma unroll
    for (int i = 0; i < NF; ++i) {
        float w = s_w0[(o<<6) | ((i + o) & 63)];
        float4 a = *(const float4*)&s_a[i*4];
        t[0] += w*a.x; t[1] += w*a.y; t[2] += w*a.z; t[3] += w*a.w;
    }
    __syncthreads();
    *(float4*)&s_a[o*4] = make_float4(lrelu(t[0]),lrelu(t[1]),lrelu(t[2]),lrelu(t[3]));
    __syncthreads();
    float u[4] = {bb1,bb1,bb1,bb1};
    #pragma unroll
    for (int i = 0; i < NF; ++i) {
        float w = s_w1[(o<<6) | ((i + o) & 63)];
        float4 a = *(const float4*)&s_a[i*4];
        u[0] += w*a.x; u[1] += w*a.y; u[2] += w*a.z; u[3] += w*a.w;
    }
    float m = 0.25f*((v[0]+0.1f*u[0]) + (v[1]+0.1f*u[1]) + (v[2]+0.1f*u[2]) + (v[3]+0.1f*u[3]));
    g_hvec[b*NF+o] = m;
}

// ---------------- latent head ----------------
__global__ void __launch_bounds__(512) k_head(
    const float* __restrict__ l1_sw, const float* __restrict__ l1_sb,
    const float* __restrict__ l1_w1, const float* __restrict__ l1_b1,
    const float* __restrict__ l1_w2, const float* __restrict__ l1_b2,
    const float* __restrict__ l2_w1, const float* __restrict__ l2_b1,
    const float* __restrict__ l2_w2, const float* __restrict__ l2_b2,
    const float* __restrict__ lo_w,  const float* __restrict__ lo_b,
    float* __restrict__ lat)
{
    __shared__ float s_h[NF], s_ha[NF];
    __shared__ float s_t[2*LATD];
    __shared__ float s_u[LATD];
    __shared__ float s_hh[LATD];
    const int j = threadIdx.x, b = blockIdx.x;
    if (j < NF) { float h = g_hvec[b*NF+j]; s_h[j] = h; s_ha[j] = lrelu(h); }
    __syncthreads();
    float xs = l1_sb[j];
    for (int i = 0; i < NF; ++i) xs += s_h[i]*l1_sw[i*LATD + j];
    float t0 = l1_b1[j], t1 = l1_b1[j+LATD];
    for (int i = 0; i < NF; ++i) {
        float a = s_ha[i];
        t0 += a*l1_w1[i*2*LATD + j];
        t1 += a*l1_w1[i*2*LATD + j + LATD];
    }
    s_t[j] = lrelu(t0); s_t[j+LATD] = lrelu(t1);
    __syncthreads();
    float v = l1_b2[j];
    for (int i = 0; i < 2*LATD; ++i) v += s_t[i]*l1_w2[(size_t)i*LATD + j];
    float hh = xs + 0.1f*v;
    s_hh[j] = hh; s_u[j] = lrelu(hh);
    __syncthreads();
    float t2 = l2_b1[j];
    for (int i = 0; i < LATD; ++i) t2 += s_u[i]*l2_w1[(size_t)i*LATD + j];
    __syncthreads();
    s_u[j] = lrelu(t2);
    __syncthreads();
    float v2 = l2_b2[j];
    for (int i = 0; i < LATD; ++i) v2 += s_u[i]*l2_w2[(size_t)i*LATD + j];
    float g = s_hh[j] + 0.1f*v2;
    s_t[j] = g;
    __syncthreads();
    float outv = lo_b[j];
    for (int i = 0; i < LATD; ++i) outv += s_t[i]*lo_w[(size_t)i*LATD + j];
    lat[b*LATD + j] = outv;
}

// ---------------- host launcher ----------------
extern "C" void kernel_launch(void* const* d_in, const int* in_sizes, int n_in,
                              void* d_out, int out_size)
{
    const float* x        = (const float*)d_in[0];
    const float* inj      = (const float*)d_in[1];
    const float* leak     = (const float*)d_in[2];
    const float* in_w     = (const float*)d_in[3];
    const float* in_b     = (const float*)d_in[4];
    const float* inrb_w0  = (const float*)d_in[5];
    const float* inrb_b0  = (const float*)d_in[6];
    const float* inrb_w1  = (const float*)d_in[7];
    const float* inrb_b1  = (const float*)d_in[8];
    const float* hyp_w    = (const float*)d_in[9];
    const float* hyp_b    = (const float*)d_in[10];
    const float* outrb_w0 = (const float*)d_in[11];
    const float* outrb_b0 = (const float*)d_in[12];
    const float* outrb_w1 = (const float*)d_in[13];
    const float* outrb_b1 = (const float*)d_in[14];
    const float* l1_sw    = (const float*)d_in[15];
    const float* l1_sb    = (const float*)d_in[16];
    const float* l1_w1    = (const float*)d_in[17];
    const float* l1_b1    = (const float*)d_in[18];
    const float* l1_w2    = (const float*)d_in[19];
    const float* l1_b2    = (const float*)d_in[20];
    const float* l2_w1    = (const float*)d_in[21];
    const float* l2_b1    = (const float*)d_in[22];
    const float* l2_w2    = (const float*)d_in[23];
    const float* l2_b2    = (const float*)d_in[24];
    const float* lo_w     = (const float*)d_in[25];
    const float* lo_b     = (const float*)d_in[26];
    float* out = (float*)d_out;

    float *p_h1, *p_h2, *p_full, *p_out, *p_wAT, *p_wMT, *p_wCDT, *p_bA, *p_bM, *p_bCD, *p_wRB;
    cudaGetSymbolAddress((void**)&p_h1,   g_h1);
    cudaGetSymbolAddress((void**)&p_h2,   g_h2);
    cudaGetSymbolAddress((void**)&p_full, g_full);
    cudaGetSymbolAddress((void**)&p_out,  g_out);
    cudaGetSymbolAddress((void**)&p_wAT,  g_wAT);
    cudaGetSymbolAddress((void**)&p_wMT,  g_wMT);
    cudaGetSymbolAddress((void**)&p_wCDT, g_wCDT);
    cudaGetSymbolAddress((void**)&p_bA,   g_bA);
    cudaGetSymbolAddress((void**)&p_bM,   g_bM);
    cudaGetSymbolAddress((void**)&p_bCD,  g_bCD);
    cudaGetSymbolAddress((void**)&p_wRB,  g_wRB);

    float* emb0 = out + (size_t)BB*LATD;   // lat occupies [0, 4096)

    // input path: y = conv1x1(x) -> g_full ; resblock via shared-weight GEMMs
    k_inconv<<<8192, 256>>>(x, in_w, in_b);
    k_trw<<<32, 256>>>(inrb_w0, inrb_w1);
    k_hyper<<<(PT/4 + 127)/128, 128>>>(inj, hyp_w, hyp_b);
    k_tr<<<dim3((61760 + 255)/256, BB), 256>>>();

    // h1 = lrelu( lrelu(y) @ w0 + b0 )
    k_gemm<256,64,0,true,0><<<dim3(P0/256, BB), 256>>>(
        p_full, NF, (long long)NF*P0, nullptr, 0, 0,
        p_wRB, NF, 0, inrb_b0, 0,
        p_h1, (long long)NF*P0, nullptr, nullptr, nullptr, P0, 128, 7);
    // out = y + 0.1*( h1 @ w1 + b1 )  -> g_out and emb0
    k_gemm<256,64,2,false,0><<<dim3(P0/256, BB), 256>>>(
        p_h1, NF, (long long)NF*P0, nullptr, 0, 0,
        p_wRB + NF*NF, NF, 0, inrb_b1, 0,
        p_out, (long long)NF*P0, emb0, p_full, nullptr, P0, 128, 7);

    size_t off = (size_t)BB*LATD + (size_t)BB*NF*P0;
    int H = 128, lgH = 7;
    for (int it = 0; it < 6; ++it) {
        int P = H*H;
        // h1 = lrelu( sobel(out) @ wA + bA )   (sobel fused into A staging)
        k_gemm<128,128,0,false,1><<<dim3((P + 127)/128, BB), 256>>>(
            p_out, FIN, (long long)NF*P, nullptr, 0, 0,
            p_wAT, FH, (long long)FIN*FH, p_bA, FH,
            p_h1, (long long)FH*P, nullptr, nullptr, nullptr, P, H, lgH);
        k_gemm<128,128,0,false,0><<<dim3((P + 127)/128, BB), 256>>>(
            p_h1, FH, (long long)FH*P, nullptr, 0, 0,
            p_wMT, FH, (long long)FH*FH, p_bM, FH,
            p_h2, (long long)FH*P, nullptr, nullptr, nullptr, P, H, lgH);
        // full = out + leak*( [h2 ; sobel(out)] @ wCD + bCD )
        k_gemm<256,64,1,false,2><<<dim3((P + 255)/256, BB), 256>>>(
            p_h2, FH, (long long)FH*P, p_out, FIN, (long long)NF*P,
            p_wCDT, NF, (long long)320*NF, p_bCD, NF,
            p_full, (long long)NF*P, nullptr, p_out, leak, P, H, lgH);
        int Hn = H/2, Pn = Hn*Hn;
        k_down<<<(BB*NF*Pn + 255)/256, 256>>>(H, lgH, out + off);
        off += (size_t)BB*NF*Pn;
        H = Hn; lgH -= 1;
    }
    k_tail<<<BB, 64>>>(outrb_w0, outrb_b0, outrb_w1, outrb_b1);
    k_head<<<BB, 512>>>(l1_sw, l1_sb, l1_w1, l1_b1, l1_w2, l1_b2,
                        l2_w1, l2_b1, l2_w2, l2_b2, lo_w, lo_b, out);
}

// round 10
// speedup vs baseline: 1.0883x; 1.0883x over previous
#include <cuda_runtime.h>
#include <cstddef>
#include <cstdint>

#define BB   8
#define NF   64
#define FIN  192
#define FH   128
#define LATD 512
#define PT   61824
#define P0   16384   // 128*128

// ---------------- scratch (device globals; no allocation) ----------------
__device__ float g_out [BB*NF *P0];
__device__ float g_perc[BB*FIN*P0];
__device__ float g_h1  [BB*FH *P0];
__device__ float g_h2  [BB*FH *P0];
__device__ float g_full[BB*NF *P0];
__device__ float g_dyn [BB*PT];
__device__ float g_wAT [BB*FIN*FH];   // [192][128] per sample (w_in^T)
__device__ float g_wMT [BB*FH*FH];    // [128][128] per sample (w_mid^T)
__device__ float g_wCDT[BB*320*NF];   // [320][64]: rows 0..127 w_out^T, 128..319 w_sk^T
__device__ float g_bA  [BB*FH];
__device__ float g_bM  [BB*FH];
__device__ float g_bCD [BB*NF];
__device__ float g_hvec[BB*NF];
__device__ float g_wRB [2*NF*NF];     // transposed inrb_w0, inrb_w1 (shared across batch)

__device__ __forceinline__ float lrelu(float x){ return x > 0.0f ? x : 0.2f*x; }
__device__ __forceinline__ float4 lrelu4(float4 v){
    return make_float4(lrelu(v.x), lrelu(v.y), lrelu(v.z), lrelu(v.w));
}
__device__ __forceinline__ void fma2(unsigned long long &d, unsigned long long a, unsigned long long b) {
    asm("fma.rn.f32x2 %0, %1, %2, %0;" : "+l"(d) : "l"(a), "l"(b));
}
__device__ __forceinline__ float2 unpack2(unsigned long long v) {
    float2 r; asm("mov.b64 {%0,%1}, %2;" : "=f"(r.x), "=f"(r.y) : "l"(v)); return r;
}
__device__ __forceinline__ unsigned long long pack2(float lo, float hi) {
    unsigned long long r; asm("mov.b64 %0, {%1,%2};" : "=l"(r) : "f"(lo), "f"(hi)); return r;
}

// ---------------- input 1x1 conv (3 -> 64): y -> g_full ----------------
__global__ void k_inconv(const float* __restrict__ x, const float* __restrict__ in_w,
                         const float* __restrict__ in_b)
{
    const int idx = blockIdx.x*256 + threadIdx.x;   // BB*NF*P0/4 = 2^21
    const int p4 = (idx & 4095) << 2;
    const int o  = (idx >> 12) & 63;
    const int b  = idx >> 18;
    const float w0 = in_w[o*3+0], w1 = in_w[o*3+1], w2 = in_w[o*3+2], bv = in_b[o];
    const float* xp = x + (size_t)(b*3)*P0 + p4;
    float4 a = *(const float4*)xp;
    float4 c = *(const float4*)(xp + P0);
    float4 d = *(const float4*)(xp + 2*P0);
    float4 r;
    r.x = bv + w0*a.x + w1*c.x + w2*d.x;
    r.y = bv + w0*a.y + w1*c.y + w2*d.y;
    r.z = bv + w0*a.z + w1*c.z + w2*d.z;
    r.w = bv + w0*a.w + w1*c.w + w2*d.w;
    *(float4*)&g_full[(size_t)(b*NF+o)*P0 + p4] = r;
}

// ---------------- transpose static resblock weights ----------------
__global__ void k_trw(const float* __restrict__ w0, const float* __restrict__ w1)
{
    const int i = blockIdx.x*256 + threadIdx.x;   // 8192
    if (i < 4096) { int k = i >> 6, o = i & 63; g_wRB[i] = w0[o*64 + k]; }
    else { int j = i - 4096; int k = j >> 6, o = j & 63; g_wRB[i] = w1[o*64 + k]; }
}

// ------- hypernet: dyn = inj_lat @ hyp_w + hyp_b (float4, batch-split grid) -----
__global__ void k_hyper(const float* __restrict__ inj, const float* __restrict__ hw,
                        const float* __restrict__ hb)
{
    __shared__ float s_inj[4*LATD];
    const int tid = threadIdx.x;  // 128
    const int b0 = blockIdx.y * 4;
    for (int e = tid; e < 4*LATD; e += 128) s_inj[e] = inj[b0*LATD + e];
    __syncthreads();
    const int j4 = (blockIdx.x*128 + tid) * 4;
    if (j4 >= PT) return;
    float4 acc[4];
    #pragma unroll
    for (int b = 0; b < 4; ++b) acc[b] = make_float4(0.f,0.f,0.f,0.f);
    for (int k = 0; k < LATD; ++k) {
        float4 w = *(const float4*)&hw[(size_t)k*PT + j4];
        #pragma unroll
        for (int b = 0; b < 4; ++b) {
            float s = s_inj[b*LATD+k];
            acc[b].x += s*w.x; acc[b].y += s*w.y;
            acc[b].z += s*w.z; acc[b].w += s*w.w;
        }
    }
    float4 bb = *(const float4*)&hb[j4];
    #pragma unroll
    for (int b = 0; b < 4; ++b) {
        float4 r = make_float4(acc[b].x+bb.x, acc[b].y+bb.y, acc[b].z+bb.z, acc[b].w+bb.w);
        *(float4*)&g_dyn[(size_t)(b0+b)*PT + j4] = r;
    }
}

// ---------------- transpose dyn params into GEMM-friendly layout ----------------
__global__ void k_tr()
{
    const int b = blockIdx.y;
    int i = blockIdx.x*256 + threadIdx.x;
    const float* d = g_dyn + (size_t)b*PT;
    if (i < FIN*FH) { int k = i/FH, o = i%FH; g_wAT[(size_t)b*FIN*FH + i] = d[o*FIN + k]; return; }
    i -= FIN*FH;
    if (i < FH*FH)  { int k = i/FH, o = i%FH; g_wMT[(size_t)b*FH*FH + i] = d[24704 + o*FH + k]; return; }
    i -= FH*FH;
    if (i < 320*NF) { int k = i/NF, o = i%NF;
        g_wCDT[(size_t)b*320*NF + i] = (k < FH) ? d[41216 + o*FH + k]
                                                : d[49472 + o*FIN + (k-FH)];
        return; }
    i -= 320*NF;
    if (i < FH) { g_bA[b*FH+i] = d[24576+i]; return; }
    i -= FH;
    if (i < FH) { g_bM[b*FH+i] = d[41088+i]; return; }
    i -= FH;
    if (i < NF) { g_bCD[b*NF+i] = d[49408+i] + d[61760+i]; return; }
}

// ---------------- sin_sobel: g_out -> g_perc, 4 px/thread ----------------
__global__ void k_sobel4(int H, int lgH)
{
    const int P = H*H;
    const int idx = blockIdx.x*256 + threadIdx.x;
    if (idx >= BB*NF*(P>>2)) return;
    const int q  = idx & ((P>>2)-1);
    const int c  = (idx >> (2*lgH-2)) & 63;
    const int b  = idx >> (2*lgH+4);
    const int p4 = q << 2;
    const int y  = p4 >> lgH, x0 = p4 & (H-1);
    const float* src = g_out + (size_t)(b*NF+c)*P;

    float am[6], ac[6], ap[6];
    {
        float4 v = *(const float4*)&src[p4];
        ac[0] = (x0 > 0)     ? src[p4-1] : 0.f;
        ac[1] = v.x; ac[2] = v.y; ac[3] = v.z; ac[4] = v.w;
        ac[5] = (x0+4 < H)   ? src[p4+4] : 0.f;
    }
    if (y > 0) {
        int base = (y-1) << lgH;
        float4 v = *(const float4*)&src[base + x0];
        am[0] = (x0 > 0)   ? src[base+x0-1] : 0.f;
        am[1] = v.x; am[2] = v.y; am[3] = v.z; am[4] = v.w;
        am[5] = (x0+4 < H) ? src[base+x0+4] : 0.f;
    } else { am[0]=am[1]=am[2]=am[3]=am[4]=am[5]=0.f; }
    if (y < H-1) {
        int base = (y+1) << lgH;
        float4 v = *(const float4*)&src[base + x0];
        ap[0] = (x0 > 0)   ? src[base+x0-1] : 0.f;
        ap[1] = v.x; ap[2] = v.y; ap[3] = v.z; ap[4] = v.w;
        ap[5] = (x0+4 < H) ? src[base+x0+4] : 0.f;
    } else { ap[0]=ap[1]=ap[2]=ap[3]=ap[4]=ap[5]=0.f; }

    float sx[4], sy[4];
    #pragma unroll
    for (int i = 0; i < 4; ++i) {
        float m00 = am[i], m01 = am[i+1], m02 = am[i+2];
        float m10 = ac[i],               m12 = ac[i+2];
        float m20 = ap[i], m21 = ap[i+1], m22 = ap[i+2];
        sx[i] = (m00 - m02 + 2.f*(m10 - m12) + m20 - m22) * 0.125f;
        sy[i] = (m00 + 2.f*m01 + m02 - m20 - 2.f*m21 - m22) * 0.125f;
    }
    float* dst = g_perc + (size_t)b*FIN*P;
    *(float4*)&dst[(size_t) c      *P + p4] = make_float4(ac[1],ac[2],ac[3],ac[4]);
    *(float4*)&dst[(size_t)(NF+c)  *P + p4] = make_float4(sx[0],sx[1],sx[2],sx[3]);
    *(float4*)&dst[(size_t)(2*NF+c)*P + p4] = make_float4(sy[0],sy[1],sy[2],sy[3]);
}

// ---------------- SGEMM: C[n][p] = sum_k A[k][p] * Wt[k][n] (+epilogue) ----------
// 256 threads, per-thread 8M x 8N via fma.rn.f32x2 (M packed in pairs).
// Plain W in smem; (w,w) duplication in registers (ALU pipe). BK=32 with
// dynamic smem halves barrier count vs BK=16; per-kc structure unchanged.
// EPI 0: C = lrelu(v+bias)
// EPI 1: C = O + clip(*leak)*(v+bias)
// EPI 2: C = O + 0.1*(v+bias), dual-store to C2
// ACT : apply lrelu to A elements when staging to smem
template<int BM, int BN, int EPI, bool ACT>
__global__ void __launch_bounds__(256, 1) k_gemm(
    const float* __restrict__ A1, int K1, long long sA1,
    const float* __restrict__ A2, int K2, long long sA2,
    const float* __restrict__ Wt, int ldw, long long sW,
    const float* __restrict__ bias, int sBias,
    float* __restrict__ C, long long sC,
    float* __restrict__ C2,
    const float* __restrict__ O, const float* __restrict__ leak_ptr,
    int P)
{
    constexpr int BK  = 32;
    constexpr int TMC = BM/8;              // threads along M
    constexpr int NA  = BK*BM/1024;        // float4 A loads per thread
    constexpr int NW  = (BK*BN >= 1024) ? BK*BN/1024 : 1;  // float4 W loads per thread

    extern __shared__ float smem[];
    float (*As)[BK][BM] = (float(*)[BK][BM])smem;
    float (*Ws)[BK][BN] = (float(*)[BK][BN])(smem + 2*BK*BM);

    const int b  = blockIdx.y;
    const int m0 = blockIdx.x * BM;
    A1 += (size_t)b * sA1;
    if (A2) A2 += (size_t)b * sA2;
    Wt   += (size_t)b * sW;
    bias += (size_t)b * sBias;

    const int tid = threadIdx.x;
    const int tm = tid % TMC;
    const int tn = tid / TMC;

    unsigned long long acc[2][2][4][2];
    #pragma unroll
    for (int af = 0; af < 2; ++af)
        #pragma unroll
        for (int wf = 0; wf < 2; ++wf)
            #pragma unroll
            for (int j = 0; j < 4; ++j) { acc[af][wf][j][0] = 0ULL; acc[af][wf][j][1] = 0ULL; }

    const int K = K1 + K2;
    const int T = K / BK;

    float4 pa[NA], pw[NW];
    auto prefetch = [&](int k0) {
        #pragma unroll
        for (int l = 0; l < NA; ++l) {
            int f  = tid + l*256;
            int kc = f / (BM/4);
            int mv = (f % (BM/4)) * 4;
            int kk = k0 + kc;
            int m  = m0 + mv;
            const float* src = (kk < K1) ? (A1 + (size_t)kk*P) : (A2 + (size_t)(kk-K1)*P);
            pa[l] = (m < P) ? *(const float4*)(src + m) : make_float4(0.f,0.f,0.f,0.f);
        }
        #pragma unroll
        for (int l = 0; l < NW; ++l) {
            int f  = tid + l*256;
            int kc = f / (BN/4);
            int nv = (f % (BN/4)) * 4;
            pw[l] = *(const float4*)(Wt + (size_t)(k0+kc)*ldw + nv);
        }
    };
    auto store_tile = [&](int nb) {
        #pragma unroll
        for (int l = 0; l < NA; ++l) {
            int f  = tid + l*256;
            int kc = f / (BM/4);
            int mv = (f % (BM/4)) * 4;
            *(float4*)&As[nb][kc][mv] = ACT ? lrelu4(pa[l]) : pa[l];
        }
        #pragma unroll
        for (int l = 0; l < NW; ++l) {
            int f  = tid + l*256;
            int kc = f / (BN/4);
            int nv = (f % (BN/4)) * 4;
            *(float4*)&Ws[nb][kc][nv] = pw[l];
        }
    };

    prefetch(0);
    store_tile(0);
    __syncthreads();

    for (int t = 0; t < T; ++t) {
        const int buf = t & 1;
        if (t + 1 < T) prefetch((t + 1) * BK);
        #pragma unroll
        for (int kc = 0; kc < BK; ++kc) {
            ulonglong2 aA = *(const ulonglong2*)&As[buf][kc][tm*4];
            ulonglong2 aB = *(const ulonglong2*)&As[buf][kc][BM/2 + tm*4];
            float4 wa = *(const float4*)&Ws[buf][kc][tn*4];
            float4 wb = *(const float4*)&Ws[buf][kc][BN/2 + tn*4];
            unsigned long long wd[2][4];
            wd[0][0] = pack2(wa.x, wa.x); wd[0][1] = pack2(wa.y, wa.y);
            wd[0][2] = pack2(wa.z, wa.z); wd[0][3] = pack2(wa.w, wa.w);
            wd[1][0] = pack2(wb.x, wb.x); wd[1][1] = pack2(wb.y, wb.y);
            wd[1][2] = pack2(wb.z, wb.z); wd[1][3] = pack2(wb.w, wb.w);
            #pragma unroll
            for (int wf = 0; wf < 2; ++wf)
                #pragma unroll
                for (int j = 0; j < 4; ++j) {
                    fma2(acc[0][wf][j][0], wd[wf][j], aA.x);
                    fma2(acc[0][wf][j][1], wd[wf][j], aA.y);
                    fma2(acc[1][wf][j][0], wd[wf][j], aB.x);
                    fma2(acc[1][wf][j][1], wd[wf][j], aB.y);
                }
        }
        if (t + 1 < T) store_tile(buf ^ 1);
        __syncthreads();
    }

    float lk = 0.1f;
    if (EPI == 1) { lk = *leak_ptr; lk = fminf(fmaxf(lk, 0.001f), 1000.f); }
    #pragma unroll
    for (int af = 0; af < 2; ++af) {
        const int m = m0 + (af ? BM/2 : 0) + tm*4;
        if (m >= P) continue;
        #pragma unroll
        for (int wf = 0; wf < 2; ++wf) {
            #pragma unroll
            for (int j = 0; j < 4; ++j) {
                const int n = (wf ? BN/2 : 0) + tn*4 + j;
                const float bv = bias[n];
                float2 p0 = unpack2(acc[af][wf][j][0]);
                float2 p1 = unpack2(acc[af][wf][j][1]);
                float4 v = make_float4(p0.x+bv, p0.y+bv, p1.x+bv, p1.y+bv);
                const size_t off = (size_t)b*sC + (size_t)n*P + m;
                if (EPI == 0) {
                    *(float4*)&C[off] = lrelu4(v);
                } else {
                    float4 o = *(const float4*)&O[off];
                    v.x = o.x + lk*v.x; v.y = o.y + lk*v.y;
                    v.z = o.z + lk*v.z; v.w = o.w + lk*v.w;
                    *(float4*)&C[off] = v;
                    if (EPI == 2) *(float4*)&C2[off] = v;
                }
            }
        }
    }
}

// ---------------- gauss 3x3 (zero pad) + 2x2 mean, writes g_out + emb ----------------
__global__ void k_down(int H, int lgH, float* __restrict__ emb)
{
    const int Hn = H >> 1, Pn = Hn*Hn;
    const int lgHn = lgH - 1;
    const int idx = blockIdx.x*256 + threadIdx.x;
    if (idx >= BB*NF*Pn) return;
    const int p = idx & (Pn-1);
    const int c = (idx >> (2*lgHn)) & (NF-1);
    const int b = idx >> (2*lgHn + 6);
    const int oy = p >> lgHn, ox = p & (Hn-1);
    const float* src = g_full + (size_t)(b*NF+c)*H*H;
    const float G0 = 0.27406861906119695f;
    const float G1 = 0.72593138093880305f;
    const float u4[4] = {G0, G1, G1, G0};
    float acc = 0.f;
    #pragma unroll
    for (int r = 0; r < 4; ++r) {
        int yy = 2*oy + r - 1;
        if (yy < 0 || yy >= H) continue;
        float rowacc = 0.f;
        #pragma unroll
        for (int cc = 0; cc < 4; ++cc) {
            int xx = 2*ox + cc - 1;
            if (xx < 0 || xx >= H) continue;
            rowacc += u4[cc]*src[(yy<<lgH)+xx];
        }
        acc += u4[r]*rowacc;
    }
    acc *= 0.25f;
    const size_t o = (size_t)(b*NF+c)*Pn + p;
    g_out[o] = acc;
    emb[o]   = acc;
}

// ---------------- tail res_block at 2x2 + spatial mean -> g_hvec ----------------
__global__ void k_tail(const float* __restrict__ w0, const float* __restrict__ b0,
                       const float* __restrict__ w1, const float* __restrict__ b1)
{
    __shared__ float s_w0[NF*NF], s_w1[NF*NF], s_a[NF*4];
    const int o = threadIdx.x, b = blockIdx.x;
    for (int e = o; e < NF*NF; e += 64) {
        int r = e >> 6, i = e & 63;
        s_w0[(r<<6) | ((i + r) & 63)] = w0[e];
        s_w1[(r<<6) | ((i + r) & 63)] = w1[e];
    }
    const float bb0 = b0[o], bb1 = b1[o];
    __syncthreads();
    float v[4];
    #pragma unroll
    for (int py = 0; py < 4; ++py) v[py] = g_out[(size_t)(b*NF+o)*4 + py];
    *(float4*)&s_a[o*4] = make_float4(lrelu(v[0]),lrelu(v[1]),lrelu(v[2]),lrelu(v[3]));
    __syncthreads();
    float t[4] = {bb0,bb0,bb0,bb0};
    #pragma unroll
    for (int i = 0; i < NF; ++i) {
        float w = s_w0[(o<<6) | ((i + o) & 63)];
        float4 a = *(const float4*)&s_a[i*4];
        t[0] += w*a.x; t[1] += w*a.y; t[2] += w*a.z; t[3] += w*a.w;
    }
    __syncthreads();
    *(float4*)&s_a[o*4] = make_float4(lrelu(t[0]),lrelu(t[1]),lrelu(t[2]),lrelu(t[3]));
    __syncthreads();
    float u[4] = {bb1,bb1,bb1,bb1};
    #pragma unroll
    for (int i = 0; i < NF; ++i) {
        float w = s_w1[(o<<6) | ((i + o) & 63)];
        float4 a = *(const float4*)&s_a[i*4];
        u[0] += w*a.x; u[1] += w*a.y; u[2] += w*a.z; u[3] += w*a.w;
    }
    float m = 0.25f*((v[0]+0.1f*u[0]) + (v[1]+0.1f*u[1]) + (v[2]+0.1f*u[2]) + (v[3]+0.1f*u[3]));
    g_hvec[b*NF+o] = m;
}

// ---------------- latent head ----------------
__global__ void __launch_bounds__(512) k_head(
    const float* __restrict__ l1_sw, const float* __restrict__ l1_sb,
    const float* __restrict__ l1_w1, const float* __restrict__ l1_b1,
    const float* __restrict__ l1_w2, const float* __restrict__ l1_b2,
    const float* __restrict__ l2_w1, const float* __restrict__ l2_b1,
    const float* __restrict__ l2_w2, const float* __restrict__ l2_b2,
    const float* __restrict__ lo_w,  const float* __restrict__ lo_b,
    float* __restrict__ lat)
{
    __shared__ float s_h[NF], s_ha[NF];
    __shared__ float s_t[2*LATD];
    __shared__ float s_u[LATD];
    __shared__ float s_hh[LATD];
    const int j = threadIdx.x, b = blockIdx.x;
    if (j < NF) { float h = g_hvec[b*NF+j]; s_h[j] = h; s_ha[j] = lrelu(h); }
    __syncthreads();
    float xs = l1_sb[j];
    for (int i = 0; i < NF; ++i) xs += s_h[i]*l1_sw[i*LATD + j];
    float t0 = l1_b1[j], t1 = l1_b1[j+LATD];
    for (int i = 0; i < NF; ++i) {
        float a = s_ha[i];
        t0 += a*l1_w1[i*2*LATD + j];
        t1 += a*l1_w1[i*2*LATD + j + LATD];
    }
    s_t[j] = lrelu(t0); s_t[j+LATD] = lrelu(t1);
    __syncthreads();
    float v = l1_b2[j];
    for (int i = 0; i < 2*LATD; ++i) v += s_t[i]*l1_w2[(size_t)i*LATD + j];
    float hh = xs + 0.1f*v;
    s_hh[j] = hh; s_u[j] = lrelu(hh);
    __syncthreads();
    float t2 = l2_b1[j];
    for (int i = 0; i < LATD; ++i) t2 += s_u[i]*l2_w1[(size_t)i*LATD + j];
    __syncthreads();
    s_u[j] = lrelu(t2);
    __syncthreads();
    float v2 = l2_b2[j];
    for (int i = 0; i < LATD; ++i) v2 += s_u[i]*l2_w2[(size_t)i*LATD + j];
    float g = s_hh[j] + 0.1f*v2;
    s_t[j] = g;
    __syncthreads();
    float outv = lo_b[j];
    for (int i = 0; i < LATD; ++i) outv += s_t[i]*lo_w[(size_t)i*LATD + j];
    lat[b*LATD + j] = outv;
}

// ---------------- host launcher ----------------
extern "C" void kernel_launch(void* const* d_in, const int* in_sizes, int n_in,
                              void* d_out, int out_size)
{
    const float* x        = (const float*)d_in[0];
    const float* inj      = (const float*)d_in[1];
    const float* leak     = (const float*)d_in[2];
    const float* in_w     = (const float*)d_in[3];
    const float* in_b     = (const float*)d_in[4];
    const float* inrb_w0  = (const float*)d_in[5];
    const float* inrb_b0  = (const float*)d_in[6];
    const float* inrb_w1  = (const float*)d_in[7];
    const float* inrb_b1  = (const float*)d_in[8];
    const float* hyp_w    = (const float*)d_in[9];
    const float* hyp_b    = (const float*)d_in[10];
    const float* outrb_w0 = (const float*)d_in[11];
    const float* outrb_b0 = (const float*)d_in[12];
    const float* outrb_w1 = (const float*)d_in[13];
    const float* outrb_b1 = (const float*)d_in[14];
    const float* l1_sw    = (const float*)d_in[15];
    const float* l1_sb    = (const float*)d_in[16];
    const float* l1_w1    = (const float*)d_in[17];
    const float* l1_b1    = (const float*)d_in[18];
    const float* l1_w2    = (const float*)d_in[19];
    const float* l1_b2    = (const float*)d_in[20];
    const float* l2_w1    = (const float*)d_in[21];
    const float* l2_b1    = (const float*)d_in[22];
    const float* l2_w2    = (const float*)d_in[23];
    const float* l2_b2    = (const float*)d_in[24];
    const float* lo_w     = (const float*)d_in[25];
    const float* lo_b     = (const float*)d_in[26];
    float* out = (float*)d_out;

    float *p_perc, *p_h1, *p_h2, *p_full, *p_out, *p_wAT, *p_wMT, *p_wCDT, *p_bA, *p_bM, *p_bCD, *p_wRB;
    cudaGetSymbolAddress((void**)&p_perc, g_perc);
    cudaGetSymbolAddress((void**)&p_h1,   g_h1);
    cudaGetSymbolAddress((void**)&p_h2,   g_h2);
    cudaGetSymbolAddress((void**)&p_full, g_full);
    cudaGetSymbolAddress((void**)&p_out,  g_out);
    cudaGetSymbolAddress((void**)&p_wAT,  g_wAT);
    cudaGetSymbolAddress((void**)&p_wMT,  g_wMT);
    cudaGetSymbolAddress((void**)&p_wCDT, g_wCDT);
    cudaGetSymbolAddress((void**)&p_bA,   g_bA);
    cudaGetSymbolAddress((void**)&p_bM,   g_bM);
    cudaGetSymbolAddress((void**)&p_bCD,  g_bCD);
    cudaGetSymbolAddress((void**)&p_wRB,  g_wRB);

    // dynamic smem sizes: (2*BK*BM + 2*BK*BN) * 4 bytes, BK=32
    const int SM_128_128 = (2*32*128 + 2*32*128) * 4;   // 64 KB
    const int SM_256_64  = (2*32*256 + 2*32*64)  * 4;   // 80 KB
    cudaFuncSetAttribute(k_gemm<256,64,0,true>,   cudaFuncAttributeMaxDynamicSharedMemorySize, SM_256_64);
    cudaFuncSetAttribute(k_gemm<256,64,2,false>,  cudaFuncAttributeMaxDynamicSharedMemorySize, SM_256_64);
    cudaFuncSetAttribute(k_gemm<256,64,1,false>,  cudaFuncAttributeMaxDynamicSharedMemorySize, SM_256_64);
    cudaFuncSetAttribute(k_gemm<128,128,0,false>, cudaFuncAttributeMaxDynamicSharedMemorySize, SM_128_128);

    float* emb0 = out + (size_t)BB*LATD;   // lat occupies [0, 4096)

    // input path: y = conv1x1(x) -> g_full ; resblock via shared-weight GEMMs
    k_inconv<<<8192, 256>>>(x, in_w, in_b);
    k_trw<<<32, 256>>>(inrb_w0, inrb_w1);
    k_hyper<<<dim3((PT/4 + 127)/128, 2), 128>>>(inj, hyp_w, hyp_b);
    k_tr<<<dim3((61760 + 255)/256, BB), 256>>>();

    // h1 = lrelu( lrelu(y) @ w0 + b0 )
    k_gemm<256,64,0,true><<<dim3(P0/256, BB), 256, SM_256_64>>>(
        p_full, NF, (long long)NF*P0, nullptr, 0, 0,
        p_wRB, NF, 0, inrb_b0, 0,
        p_h1, (long long)NF*P0, nullptr, nullptr, nullptr, P0);
    // out = y + 0.1*( h1 @ w1 + b1 )  -> g_out and emb0
    k_gemm<256,64,2,false><<<dim3(P0/256, BB), 256, SM_256_64>>>(
        p_h1, NF, (long long)NF*P0, nullptr, 0, 0,
        p_wRB + NF*NF, NF, 0, inrb_b1, 0,
        p_out, (long long)NF*P0, emb0, p_full, nullptr, P0);

    size_t off = (size_t)BB*LATD + (size_t)BB*NF*P0;
    int H = 128, lgH = 7;
    for (int it = 0; it < 6; ++it) {
        int P = H*H;
        k_sobel4<<<(BB*NF*(P/4) + 255)/256, 256>>>(H, lgH);
        k_gemm<128,128,0,false><<<dim3((P + 127)/128, BB), 256, SM_128_128>>>(
            p_perc, FIN, (long long)FIN*P, nullptr, 0, 0,
            p_wAT, FH, (long long)FIN*FH, p_bA, FH,
            p_h1, (long long)FH*P, nullptr, nullptr, nullptr, P);
        k_gemm<128,128,0,false><<<dim3((P + 127)/128, BB), 256, SM_128_128>>>(
            p_h1, FH, (long long)FH*P, nullptr, 0, 0,
            p_wMT, FH, (long long)FH*FH, p_bM, FH,
            p_h2, (long long)FH*P, nullptr, nullptr, nullptr, P);
        k_gemm<256,64,1,false><<<dim3((P + 255)/256, BB), 256, SM_256_64>>>(
            p_h2, FH, (long long)FH*P, p_perc, FIN, (long long)FIN*P,
            p_wCDT, NF, (long long)320*NF, p_bCD, NF,
            p_full, (long long)NF*P, nullptr, p_out, leak, P);
        int Hn = H/2, Pn = Hn*Hn;
        k_down<<<(BB*NF*Pn + 255)/256, 256>>>(H, lgH, out + off);
        off += (size_t)BB*NF*Pn;
        H = Hn; lgH -= 1;
    }
    k_tail<<<BB, 64>>>(outrb_w0, outrb_b0, outrb_w1, outrb_b1);
    k_head<<<BB, 512>>>(l1_sw, l1_sb, l1_w1, l1_b1, l1_w2, l1_b2,
                        l2_w1, l2_b1, l2_w2, l2_b2, lo_w, lo_b, out);
}

// round 12
// speedup vs baseline: 1.2078x; 1.1098x over previous
#include <cuda_runtime.h>
#include <cstddef>
#include <cstdint>

#define BB   8
#define NF   64
#define FIN  192
#define FH   128
#define LATD 512
#define PT   61824
#define P0   16384   // 128*128

// ---------------- scratch (device globals; no allocation) ----------------
__device__ float g_out [BB*NF *P0];
__device__ float g_perc[BB*FIN*P0];
__device__ float g_h1  [BB*FH *P0];
__device__ float g_h2  [BB*FH *P0];
__device__ float g_full[BB*NF *P0];
__device__ float g_dyn [BB*PT];
__device__ float g_wAT [BB*FIN*FH];   // [192][128] per sample (w_in^T)
__device__ float g_wMT [BB*FH*FH];    // [128][128] per sample (w_mid^T)
__device__ float g_wCDT[BB*320*NF];   // [320][64]: rows 0..127 w_out^T, 128..319 w_sk^T
__device__ float g_bA  [BB*FH];
__device__ float g_bM  [BB*FH];
__device__ float g_bCD [BB*NF];
__device__ float g_hvec[BB*NF];
__device__ float g_wRB [2*NF*NF];     // transposed inrb_w0, inrb_w1 (shared across batch)

__device__ __forceinline__ float lrelu(float x){ return x > 0.0f ? x : 0.2f*x; }
__device__ __forceinline__ float4 lrelu4(float4 v){
    return make_float4(lrelu(v.x), lrelu(v.y), lrelu(v.z), lrelu(v.w));
}
__device__ __forceinline__ void fma2(unsigned long long &d, unsigned long long a, unsigned long long b) {
    asm("fma.rn.f32x2 %0, %1, %2, %0;" : "+l"(d) : "l"(a), "l"(b));
}
__device__ __forceinline__ float2 unpack2(unsigned long long v) {
    float2 r; asm("mov.b64 {%0,%1}, %2;" : "=f"(r.x), "=f"(r.y) : "l"(v)); return r;
}
__device__ __forceinline__ unsigned long long pack2(float lo, float hi) {
    unsigned long long r; asm("mov.b64 %0, {%1,%2};" : "=l"(r) : "f"(lo), "f"(hi)); return r;
}

// ---------------- input 1x1 conv (3 -> 64): y -> g_full ----------------
__global__ void k_inconv(const float* __restrict__ x, const float* __restrict__ in_w,
                         const float* __restrict__ in_b)
{
    const int idx = blockIdx.x*256 + threadIdx.x;   // BB*NF*P0/4 = 2^21
    const int p4 = (idx & 4095) << 2;
    const int o  = (idx >> 12) & 63;
    const int b  = idx >> 18;
    const float w0 = in_w[o*3+0], w1 = in_w[o*3+1], w2 = in_w[o*3+2], bv = in_b[o];
    const float* xp = x + (size_t)(b*3)*P0 + p4;
    float4 a = *(const float4*)xp;
    float4 c = *(const float4*)(xp + P0);
    float4 d = *(const float4*)(xp + 2*P0);
    float4 r;
    r.x = bv + w0*a.x + w1*c.x + w2*d.x;
    r.y = bv + w0*a.y + w1*c.y + w2*d.y;
    r.z = bv + w0*a.z + w1*c.z + w2*d.z;
    r.w = bv + w0*a.w + w1*c.w + w2*d.w;
    *(float4*)&g_full[(size_t)(b*NF+o)*P0 + p4] = r;
}

// ---------------- transpose static resblock weights ----------------
__global__ void k_trw(const float* __restrict__ w0, const float* __restrict__ w1)
{
    const int i = blockIdx.x*256 + threadIdx.x;   // 8192
    if (i < 4096) { int k = i >> 6, o = i & 63; g_wRB[i] = w0[o*64 + k]; }
    else { int j = i - 4096; int k = j >> 6, o = j & 63; g_wRB[i] = w1[o*64 + k]; }
}

// ------- hypernet: dyn = inj_lat @ hyp_w + hyp_b (float4, batch-split grid) -----
__global__ void k_hyper(const float* __restrict__ inj, const float* __restrict__ hw,
                        const float* __restrict__ hb)
{
    __shared__ float s_inj[4*LATD];
    const int tid = threadIdx.x;  // 128
    const int b0 = blockIdx.y * 4;
    for (int e = tid; e < 4*LATD; e += 128) s_inj[e] = inj[b0*LATD + e];
    __syncthreads();
    const int j4 = (blockIdx.x*128 + tid) * 4;
    if (j4 >= PT) return;
    float4 acc[4];
    #pragma unroll
    for (int b = 0; b < 4; ++b) acc[b] = make_float4(0.f,0.f,0.f,0.f);
    for (int k = 0; k < LATD; ++k) {
        float4 w = *(const float4*)&hw[(size_t)k*PT + j4];
        #pragma unroll
        for (int b = 0; b < 4; ++b) {
            float s = s_inj[b*LATD+k];
            acc[b].x += s*w.x; acc[b].y += s*w.y;
            acc[b].z += s*w.z; acc[b].w += s*w.w;
        }
    }
    float4 bb = *(const float4*)&hb[j4];
    #pragma unroll
    for (int b = 0; b < 4; ++b) {
        float4 r = make_float4(acc[b].x+bb.x, acc[b].y+bb.y, acc[b].z+bb.z, acc[b].w+bb.w);
        *(float4*)&g_dyn[(size_t)(b0+b)*PT + j4] = r;
    }
}

// ---------------- transpose dyn params into GEMM-friendly layout ----------------
__global__ void k_tr()
{
    const int b = blockIdx.y;
    int i = blockIdx.x*256 + threadIdx.x;
    const float* d = g_dyn + (size_t)b*PT;
    if (i < FIN*FH) { int k = i/FH, o = i%FH; g_wAT[(size_t)b*FIN*FH + i] = d[o*FIN + k]; return; }
    i -= FIN*FH;
    if (i < FH*FH)  { int k = i/FH, o = i%FH; g_wMT[(size_t)b*FH*FH + i] = d[24704 + o*FH + k]; return; }
    i -= FH*FH;
    if (i < 320*NF) { int k = i/NF, o = i%NF;
        g_wCDT[(size_t)b*320*NF + i] = (k < FH) ? d[41216 + o*FH + k]
                                                : d[49472 + o*FIN + (k-FH)];
        return; }
    i -= 320*NF;
    if (i < FH) { g_bA[b*FH+i] = d[24576+i]; return; }
    i -= FH;
    if (i < FH) { g_bM[b*FH+i] = d[41088+i]; return; }
    i -= FH;
    if (i < NF) { g_bCD[b*NF+i] = d[49408+i] + d[61760+i]; return; }
}

// ---------------- sin_sobel: g_out -> g_perc, 4 px/thread ----------------
__global__ void k_sobel4(int H, int lgH)
{
    const int P = H*H;
    const int idx = blockIdx.x*256 + threadIdx.x;
    if (idx >= BB*NF*(P>>2)) return;
    const int q  = idx & ((P>>2)-1);
    const int c  = (idx >> (2*lgH-2)) & 63;
    const int b  = idx >> (2*lgH+4);
    const int p4 = q << 2;
    const int y  = p4 >> lgH, x0 = p4 & (H-1);
    const float* src = g_out + (size_t)(b*NF+c)*P;

    float am[6], ac[6], ap[6];
    {
        float4 v = *(const float4*)&src[p4];
        ac[0] = (x0 > 0)     ? src[p4-1] : 0.f;
        ac[1] = v.x; ac[2] = v.y; ac[3] = v.z; ac[4] = v.w;
        ac[5] = (x0+4 < H)   ? src[p4+4] : 0.f;
    }
    if (y > 0) {
        int base = (y-1) << lgH;
        float4 v = *(const float4*)&src[base + x0];
        am[0] = (x0 > 0)   ? src[base+x0-1] : 0.f;
        am[1] = v.x; am[2] = v.y; am[3] = v.z; am[4] = v.w;
        am[5] = (x0+4 < H) ? src[base+x0+4] : 0.f;
    } else { am[0]=am[1]=am[2]=am[3]=am[4]=am[5]=0.f; }
    if (y < H-1) {
        int base = (y+1) << lgH;
        float4 v = *(const float4*)&src[base + x0];
        ap[0] = (x0 > 0)   ? src[base+x0-1] : 0.f;
        ap[1] = v.x; ap[2] = v.y; ap[3] = v.z; ap[4] = v.w;
        ap[5] = (x0+4 < H) ? src[base+x0+4] : 0.f;
    } else { ap[0]=ap[1]=ap[2]=ap[3]=ap[4]=ap[5]=0.f; }

    float sx[4], sy[4];
    #pragma unroll
    for (int i = 0; i < 4; ++i) {
        float m00 = am[i], m01 = am[i+1], m02 = am[i+2];
        float m10 = ac[i],               m12 = ac[i+2];
        float m20 = ap[i], m21 = ap[i+1], m22 = ap[i+2];
        sx[i] = (m00 - m02 + 2.f*(m10 - m12) + m20 - m22) * 0.125f;
        sy[i] = (m00 + 2.f*m01 + m02 - m20 - 2.f*m21 - m22) * 0.125f;
    }
    float* dst = g_perc + (size_t)b*FIN*P;
    *(float4*)&dst[(size_t) c      *P + p4] = make_float4(ac[1],ac[2],ac[3],ac[4]);
    *(float4*)&dst[(size_t)(NF+c)  *P + p4] = make_float4(sx[0],sx[1],sx[2],sx[3]);
    *(float4*)&dst[(size_t)(2*NF+c)*P + p4] = make_float4(sy[0],sy[1],sy[2],sy[3]);
}

// ---------------- SGEMM: C[n][p] = sum_k A[k][p] * Wt[k][n] (+epilogue) ----------
// 256 threads, per-thread MT x 8N via fma.rn.f32x2 (M packed in pairs).
// MT=8 (default): BMxBN grid tile, blockIdx.x = tileM only (tilesN=1 use).
// MT=4 (small-P): BM=128,BN=64 small tiles; blockIdx.x = tileM + tileN*tilesM.
// EPI 0: C = lrelu(v+bias)
// EPI 1: C = O + clip(*leak)*(v+bias)
// EPI 2: C = O + 0.1*(v+bias), dual-store to C2
// ACT : apply lrelu to A elements when staging to smem
template<int BM, int BN, int EPI, bool ACT, int MT>
__global__ void __launch_bounds__(256, 1) k_gemm(
    const float* __restrict__ A1, int K1, long long sA1,
    const float* __restrict__ A2, int K2, long long sA2,
    const float* __restrict__ Wt, int ldw, long long sW,
    const float* __restrict__ bias, int sBias,
    float* __restrict__ C, long long sC,
    float* __restrict__ C2,
    const float* __restrict__ O, const float* __restrict__ leak_ptr,
    int P, int tilesM)
{
    constexpr int BK  = 32;
    constexpr int TMC = BM/MT;             // threads along M
    constexpr int NA  = BK*BM/1024;        // float4 A loads per thread
    constexpr int NW  = (BK*BN >= 1024) ? BK*BN/1024 : 1;

    extern __shared__ float smem[];
    float (*As)[BK][BM] = (float(*)[BK][BM])smem;
    float (*Ws)[BK][BN] = (float(*)[BK][BN])(smem + 2*BK*BM);

    const int b  = blockIdx.y;
    const int m0 = (blockIdx.x % tilesM) * BM;
    const int n0 = (blockIdx.x / tilesM) * BN;
    A1 += (size_t)b * sA1;
    if (A2) A2 += (size_t)b * sA2;
    Wt   += (size_t)b * sW;
    bias += (size_t)b * sBias;

    const int tid = threadIdx.x;
    const int tm = tid % TMC;
    const int tn = tid / TMC;

    constexpr int AF = MT/4;
    unsigned long long acc[AF][2][4][2];
    #pragma unroll
    for (int af = 0; af < AF; ++af)
        #pragma unroll
        for (int wf = 0; wf < 2; ++wf)
            #pragma unroll
            for (int j = 0; j < 4; ++j) { acc[af][wf][j][0] = 0ULL; acc[af][wf][j][1] = 0ULL; }

    const int K = K1 + K2;
    const int T = K / BK;

    float4 pa[NA], pw[NW];
    auto prefetch = [&](int k0) {
        #pragma unroll
        for (int l = 0; l < NA; ++l) {
            int f  = tid + l*256;
            int kc = f / (BM/4);
            int mv = (f % (BM/4)) * 4;
            int kk = k0 + kc;
            int m  = m0 + mv;
            const float* src = (kk < K1) ? (A1 + (size_t)kk*P) : (A2 + (size_t)(kk-K1)*P);
            pa[l] = (m < P) ? *(const float4*)(src + m) : make_float4(0.f,0.f,0.f,0.f);
        }
        #pragma unroll
        for (int l = 0; l < NW; ++l) {
            int f  = tid + l*256;
            int kc = f / (BN/4);
            int nv = (f % (BN/4)) * 4;
            pw[l] = *(const float4*)(Wt + (size_t)(k0+kc)*ldw + n0 + nv);
        }
    };
    auto store_tile = [&](int nb) {
        #pragma unroll
        for (int l = 0; l < NA; ++l) {
            int f  = tid + l*256;
            int kc = f / (BM/4);
            int mv = (f % (BM/4)) * 4;
            *(float4*)&As[nb][kc][mv] = ACT ? lrelu4(pa[l]) : pa[l];
        }
        #pragma unroll
        for (int l = 0; l < NW; ++l) {
            int f  = tid + l*256;
            int kc = f / (BN/4);
            int nv = (f % (BN/4)) * 4;
            *(float4*)&Ws[nb][kc][nv] = pw[l];
        }
    };

    prefetch(0);
    store_tile(0);
    __syncthreads();

    for (int t = 0; t < T; ++t) {
        const int buf = t & 1;
        if (t + 1 < T) prefetch((t + 1) * BK);
        #pragma unroll
        for (int kc = 0; kc < BK; ++kc) {
            ulonglong2 aA = *(const ulonglong2*)&As[buf][kc][tm*4];
            ulonglong2 aB;
            if (MT == 8) aB = *(const ulonglong2*)&As[buf][kc][BM/2 + tm*4];
            float4 wa = *(const float4*)&Ws[buf][kc][tn*4];
            float4 wb = *(const float4*)&Ws[buf][kc][BN/2 + tn*4];
            unsigned long long wd[2][4];
            wd[0][0] = pack2(wa.x, wa.x); wd[0][1] = pack2(wa.y, wa.y);
            wd[0][2] = pack2(wa.z, wa.z); wd[0][3] = pack2(wa.w, wa.w);
            wd[1][0] = pack2(wb.x, wb.x); wd[1][1] = pack2(wb.y, wb.y);
            wd[1][2] = pack2(wb.z, wb.z); wd[1][3] = pack2(wb.w, wb.w);
            #pragma unroll
            for (int wf = 0; wf < 2; ++wf)
                #pragma unroll
                for (int j = 0; j < 4; ++j) {
                    fma2(acc[0][wf][j][0], wd[wf][j], aA.x);
                    fma2(acc[0][wf][j][1], wd[wf][j], aA.y);
                    if (MT == 8) {
                        fma2(acc[AF-1][wf][j][0], wd[wf][j], aB.x);
                        fma2(acc[AF-1][wf][j][1], wd[wf][j], aB.y);
                    }
                }
        }
        if (t + 1 < T) store_tile(buf ^ 1);
        __syncthreads();
    }

    float lk = 0.1f;
    if (EPI == 1) { lk = *leak_ptr; lk = fminf(fmaxf(lk, 0.001f), 1000.f); }
    #pragma unroll
    for (int af = 0; af < AF; ++af) {
        const int m = m0 + (af ? BM/2 : 0) + tm*4;
        if (m >= P) continue;
        #pragma unroll
        for (int wf = 0; wf < 2; ++wf) {
            #pragma unroll
            for (int j = 0; j < 4; ++j) {
                const int n = n0 + (wf ? BN/2 : 0) + tn*4 + j;
                const float bv = bias[n];
                float2 p0 = unpack2(acc[af][wf][j][0]);
                float2 p1 = unpack2(acc[af][wf][j][1]);
                float4 v = make_float4(p0.x+bv, p0.y+bv, p1.x+bv, p1.y+bv);
                const size_t off = (size_t)b*sC + (size_t)n*P + m;
                if (EPI == 0) {
                    *(float4*)&C[off] = lrelu4(v);
                } else {
                    float4 o = *(const float4*)&O[off];
                    v.x = o.x + lk*v.x; v.y = o.y + lk*v.y;
                    v.z = o.z + lk*v.z; v.w = o.w + lk*v.w;
                    *(float4*)&C[off] = v;
                    if (EPI == 2) *(float4*)&C2[off] = v;
                }
            }
        }
    }
}

// ---------------- gauss 3x3 (zero pad) + 2x2 mean, writes g_out + emb ----------------
__global__ void k_down(int H, int lgH, float* __restrict__ emb)
{
    const int Hn = H >> 1, Pn = Hn*Hn;
    const int lgHn = lgH - 1;
    const int idx = blockIdx.x*256 + threadIdx.x;
    if (idx >= BB*NF*Pn) return;
    const int p = idx & (Pn-1);
    const int c = (idx >> (2*lgHn)) & (NF-1);
    const int b = idx >> (2*lgHn + 6);
    const int oy = p >> lgHn, ox = p & (Hn-1);
    const float* src = g_full + (size_t)(b*NF+c)*H*H;
    const float G0 = 0.27406861906119695f;
    const float G1 = 0.72593138093880305f;
    const float u4[4] = {G0, G1, G1, G0};
    float acc = 0.f;
    #pragma unroll
    for (int r = 0; r < 4; ++r) {
        int yy = 2*oy + r - 1;
        if (yy < 0 || yy >= H) continue;
        float rowacc = 0.f;
        #pragma unroll
        for (int cc = 0; cc < 4; ++cc) {
            int xx = 2*ox + cc - 1;
            if (xx < 0 || xx >= H) continue;
            rowacc += u4[cc]*src[(yy<<lgH)+xx];
        }
        acc += u4[r]*rowacc;
    }
    acc *= 0.25f;
    const size_t o = (size_t)(b*NF+c)*Pn + p;
    g_out[o] = acc;
    emb[o]   = acc;
}

// ---------------- tail res_block at 2x2 + spatial mean -> g_hvec ----------------
__global__ void k_tail(const float* __restrict__ w0, const float* __restrict__ b0,
                       const float* __restrict__ w1, const float* __restrict__ b1)
{
    __shared__ float s_w0[NF*NF], s_w1[NF*NF], s_a[NF*4];
    const int o = threadIdx.x, b = blockIdx.x;
    for (int e = o; e < NF*NF; e += 64) {
        int r = e >> 6, i = e & 63;
        s_w0[(r<<6) | ((i + r) & 63)] = w0[e];
        s_w1[(r<<6) | ((i + r) & 63)] = w1[e];
    }
    const float bb0 = b0[o], bb1 = b1[o];
    __syncthreads();
    float v[4];
    #pragma unroll
    for (int py = 0; py < 4; ++py) v[py] = g_out[(size_t)(b*NF+o)*4 + py];
    *(float4*)&s_a[o*4] = make_float4(lrelu(v[0]),lrelu(v[1]),lrelu(v[2]),lrelu(v[3]));
    __syncthreads();
    float t[4] = {bb0,bb0,bb0,bb0};
    #pragma unroll
    for (int i = 0; i < NF; ++i) {
        float w = s_w0[(o<<6) | ((i + o) & 63)];
        float4 a = *(const float4*)&s_a[i*4];
        t[0] += w*a.x; t[1] += w*a.y; t[2] += w*a.z; t[3] += w*a.w;
    }
    __syncthreads();
    *(float4*)&s_a[o*4] = make_float4(lrelu(t[0]),lrelu(t[1]),lrelu(t[2]),lrelu(t[3]));
    __syncthreads();
    float u[4] = {bb1,bb1,bb1,bb1};
    #pragma unroll
    for (int i = 0; i < NF; ++i) {
        float w = s_w1[(o<<6) | ((i + o) & 63)];
        float4 a = *(const float4*)&s_a[i*4];
        u[0] += w*a.x; u[1] += w*a.y; u[2] += w*a.z; u[3] += w*a.w;
    }
    float m = 0.25f*((v[0]+0.1f*u[0]) + (v[1]+0.1f*u[1]) + (v[2]+0.1f*u[2]) + (v[3]+0.1f*u[3]));
    g_hvec[b*NF+o] = m;
}

// ---------------- latent head ----------------
__global__ void __launch_bounds__(512) k_head(
    const float* __restrict__ l1_sw, const float* __restrict__ l1_sb,
    const float* __restrict__ l1_w1, const float* __restrict__ l1_b1,
    const float* __restrict__ l1_w2, const float* __restrict__ l1_b2,
    const float* __restrict__ l2_w1, const float* __restrict__ l2_b1,
    const float* __restrict__ l2_w2, const float* __restrict__ l2_b2,
    const float* __restrict__ lo_w,  const float* __restrict__ lo_b,
    float* __restrict__ lat)
{
    __shared__ float s_h[NF], s_ha[NF];
    __shared__ float s_t[2*LATD];
    __shared__ float s_u[LATD];
    __shared__ float s_hh[LATD];
    const int j = threadIdx.x, b = blockIdx.x;
    if (j < NF) { float h = g_hvec[b*NF+j]; s_h[j] = h; s_ha[j] = lrelu(h); }
    __syncthreads();
    float xs = l1_sb[j];
    for (int i = 0; i < NF; ++i) xs += s_h[i]*l1_sw[i*LATD + j];
    float t0 = l1_b1[j], t1 = l1_b1[j+LATD];
    for (int i = 0; i < NF; ++i) {
        float a = s_ha[i];
        t0 += a*l1_w1[i*2*LATD + j];
        t1 += a*l1_w1[i*2*LATD + j + LATD];
    }
    s_t[j] = lrelu(t0); s_t[j+LATD] = lrelu(t1);
    __syncthreads();
    float v = l1_b2[j];
    for (int i = 0; i < 2*LATD; ++i) v += s_t[i]*l1_w2[(size_t)i*LATD + j];
    float hh = xs + 0.1f*v;
    s_hh[j] = hh; s_u[j] = lrelu(hh);
    __syncthreads();
    float t2 = l2_b1[j];
    for (int i = 0; i < LATD; ++i) t2 += s_u[i]*l2_w1[(size_t)i*LATD + j];
    __syncthreads();
    s_u[j] = lrelu(t2);
    __syncthreads();
    float v2 = l2_b2[j];
    for (int i = 0; i < LATD; ++i) v2 += s_u[i]*l2_w2[(size_t)i*LATD + j];
    float g = s_hh[j] + 0.1f*v2;
    s_t[j] = g;
    __syncthreads();
    float outv = lo_b[j];
    for (int i = 0; i < LATD; ++i) outv += s_t[i]*lo_w[(size_t)i*LATD + j];
    lat[b*LATD + j] = outv;
}

// ---------------- host launcher ----------------
extern "C" void kernel_launch(void* const* d_in, const int* in_sizes, int n_in,
                              void* d_out, int out_size)
{
    const float* x        = (const float*)d_in[0];
    const float* inj      = (const float*)d_in[1];
    const float* leak     = (const float*)d_in[2];
    const float* in_w     = (const float*)d_in[3];
    const float* in_b     = (const float*)d_in[4];
    const float* inrb_w0  = (const float*)d_in[5];
    const float* inrb_b0  = (const float*)d_in[6];
    const float* inrb_w1  = (const float*)d_in[7];
    const float* inrb_b1  = (const float*)d_in[8];
    const float* hyp_w    = (const float*)d_in[9];
    const float* hyp_b    = (const float*)d_in[10];
    const float* outrb_w0 = (const float*)d_in[11];
    const float* outrb_b0 = (const float*)d_in[12];
    const float* outrb_w1 = (const float*)d_in[13];
    const float* outrb_b1 = (const float*)d_in[14];
    const float* l1_sw    = (const float*)d_in[15];
    const float* l1_sb    = (const float*)d_in[16];
    const float* l1_w1    = (const float*)d_in[17];
    const float* l1_b1    = (const float*)d_in[18];
    const float* l1_w2    = (const float*)d_in[19];
    const float* l1_b2    = (const float*)d_in[20];
    const float* l2_w1    = (const float*)d_in[21];
    const float* l2_b1    = (const float*)d_in[22];
    const float* l2_w2    = (const float*)d_in[23];
    const float* l2_b2    = (const float*)d_in[24];
    const float* lo_w     = (const float*)d_in[25];
    const float* lo_b     = (const float*)d_in[26];
    float* out = (float*)d_out;

    float *p_perc, *p_h1, *p_h2, *p_full, *p_out, *p_wAT, *p_wMT, *p_wCDT, *p_bA, *p_bM, *p_bCD, *p_wRB;
    cudaGetSymbolAddress((void**)&p_perc, g_perc);
    cudaGetSymbolAddress((void**)&p_h1,   g_h1);
    cudaGetSymbolAddress((void**)&p_h2,   g_h2);
    cudaGetSymbolAddress((void**)&p_full, g_full);
    cudaGetSymbolAddress((void**)&p_out,  g_out);
    cudaGetSymbolAddress((void**)&p_wAT,  g_wAT);
    cudaGetSymbolAddress((void**)&p_wMT,  g_wMT);
    cudaGetSymbolAddress((void**)&p_wCDT, g_wCDT);
    cudaGetSymbolAddress((void**)&p_bA,   g_bA);
    cudaGetSymbolAddress((void**)&p_bM,   g_bM);
    cudaGetSymbolAddress((void**)&p_bCD,  g_bCD);
    cudaGetSymbolAddress((void**)&p_wRB,  g_wRB);

    // dynamic smem sizes: (2*BK*BM + 2*BK*BN) * 4 bytes, BK=32
    const int SM_128_128 = (2*32*128 + 2*32*128) * 4;   // 64 KB
    const int SM_256_64  = (2*32*256 + 2*32*64)  * 4;   // 80 KB
    const int SM_128_64  = (2*32*128 + 2*32*64)  * 4;   // 48 KB
    cudaFuncSetAttribute(k_gemm<256,64,0,true,8>,   cudaFuncAttributeMaxDynamicSharedMemorySize, SM_256_64);
    cudaFuncSetAttribute(k_gemm<256,64,2,false,8>,  cudaFuncAttributeMaxDynamicSharedMemorySize, SM_256_64);
    cudaFuncSetAttribute(k_gemm<256,64,1,false,8>,  cudaFuncAttributeMaxDynamicSharedMemorySize, SM_256_64);
    cudaFuncSetAttribute(k_gemm<128,128,0,false,8>, cudaFuncAttributeMaxDynamicSharedMemorySize, SM_128_128);
    cudaFuncSetAttribute(k_gemm<128,64,0,false,4>,  cudaFuncAttributeMaxDynamicSharedMemorySize, SM_128_64);
    cudaFuncSetAttribute(k_gemm<128,64,1,false,4>,  cudaFuncAttributeMaxDynamicSharedMemorySize, SM_128_64);

    float* emb0 = out + (size_t)BB*LATD;   // lat occupies [0, 4096)

    k_inconv<<<8192, 256>>>(x, in_w, in_b);
    k_trw<<<32, 256>>>(inrb_w0, inrb_w1);
    k_hyper<<<dim3((PT/4 + 127)/128, 2), 128>>>(inj, hyp_w, hyp_b);
    k_tr<<<dim3((61760 + 255)/256, BB), 256>>>();

    // h1 = lrelu( lrelu(y) @ w0 + b0 )
    k_gemm<256,64,0,true,8><<<dim3(P0/256, BB), 256, SM_256_64>>>(
        p_full, NF, (long long)NF*P0, nullptr, 0, 0,
        p_wRB, NF, 0, inrb_b0, 0,
        p_h1, (long long)NF*P0, nullptr, nullptr, nullptr, P0, P0/256);
    // out = y + 0.1*( h1 @ w1 + b1 )  -> g_out and emb0
    k_gemm<256,64,2,false,8><<<dim3(P0/256, BB), 256, SM_256_64>>>(
        p_h1, NF, (long long)NF*P0, nullptr, 0, 0,
        p_wRB + NF*NF, NF, 0, inrb_b1, 0,
        p_out, (long long)NF*P0, emb0, p_full, nullptr, P0, P0/256);

    size_t off = (size_t)BB*LATD + (size_t)BB*NF*P0;
    int H = 128, lgH = 7;
    for (int it = 0; it < 6; ++it) {
        int P = H*H;
        k_sobel4<<<(BB*NF*(P/4) + 255)/256, 256>>>(H, lgH);
        if (P > 1024) {
            int tM = (P + 127)/128;
            k_gemm<128,128,0,false,8><<<dim3(tM, BB), 256, SM_128_128>>>(
                p_perc, FIN, (long long)FIN*P, nullptr, 0, 0,
                p_wAT, FH, (long long)FIN*FH, p_bA, FH,
                p_h1, (long long)FH*P, nullptr, nullptr, nullptr, P, tM);
            k_gemm<128,128,0,false,8><<<dim3(tM, BB), 256, SM_128_128>>>(
                p_h1, FH, (long long)FH*P, nullptr, 0, 0,
                p_wMT, FH, (long long)FH*FH, p_bM, FH,
                p_h2, (long long)FH*P, nullptr, nullptr, nullptr, P, tM);
            int tM2 = (P + 255)/256;
            k_gemm<256,64,1,false,8><<<dim3(tM2, BB), 256, SM_256_64>>>(
                p_h2, FH, (long long)FH*P, p_perc, FIN, (long long)FIN*P,
                p_wCDT, NF, (long long)320*NF, p_bCD, NF,
                p_full, (long long)NF*P, nullptr, p_out, leak, P, tM2);
        } else {
            int tM = (P + 127)/128;
            // N=128 outputs: 2 N-tiles of 64
            k_gemm<128,64,0,false,4><<<dim3(tM*2, BB), 256, SM_128_64>>>(
                p_perc, FIN, (long long)FIN*P, nullptr, 0, 0,
                p_wAT, FH, (long long)FIN*FH, p_bA, FH,
                p_h1, (long long)FH*P, nullptr, nullptr, nullptr, P, tM);
            k_gemm<128,64,0,false,4><<<dim3(tM*2, BB), 256, SM_128_64>>>(
                p_h1, FH, (long long)FH*P, nullptr, 0, 0,
                p_wMT, FH, (long long)FH*FH, p_bM, FH,
                p_h2, (long long)FH*P, nullptr, nullptr, nullptr, P, tM);
            k_gemm<128,64,1,false,4><<<dim3(tM, BB), 256, SM_128_64>>>(
                p_h2, FH, (long long)FH*P, p_perc, FIN, (long long)FIN*P,
                p_wCDT, NF, (long long)320*NF, p_bCD, NF,
                p_full, (long long)NF*P, nullptr, p_out, leak, P, tM);
        }
        int Hn = H/2, Pn = Hn*Hn;
        k_down<<<(BB*NF*Pn + 255)/256, 256>>>(H, lgH, out + off);
        off += (size_t)BB*NF*Pn;
        H = Hn; lgH -= 1;
    }
    k_tail<<<BB, 64>>>(outrb_w0, outrb_b0, outrb_w1, outrb_b1);
    k_head<<<BB, 512>>>(l1_sw, l1_sb, l1_w1, l1_b1, l1_w2, l1_b2,
                        l2_w1, l2_b1, l2_w2, l2_b2, lo_w, lo_b, out);
}

// round 13
// speedup vs baseline: 1.2361x; 1.0235x over previous
#include <cuda_runtime.h>
#include <cstddef>
#include <cstdint>

#define BB   8
#define NF   64
#define FIN  192
#define FH   128
#define LATD 512
#define PT   61824
#define P0   16384   // 128*128

// ---------------- scratch (device globals; no allocation) ----------------
__device__ float g_out [BB*NF *P0];
__device__ float g_perc[BB*2*NF*P0];  // dx,dy only (identity read from g_out)
__device__ float g_h1  [BB*FH *P0];
__device__ float g_h2  [BB*FH *P0];
__device__ float g_full[BB*NF *P0];
__device__ float g_dyn [BB*PT];
__device__ float g_wAT [BB*FIN*FH];   // [192][128] per sample (w_in^T)
__device__ float g_wMT [BB*FH*FH];    // [128][128] per sample (w_mid^T)
__device__ float g_wCDT[BB*320*NF];   // [320][64]: rows 0..127 w_out^T, 128..319 w_sk^T
__device__ float g_bA  [BB*FH];
__device__ float g_bM  [BB*FH];
__device__ float g_bCD [BB*NF];
__device__ float g_hvec[BB*NF];
__device__ float g_wRB [2*NF*NF];     // transposed inrb_w0, inrb_w1 (shared across batch)

__device__ __forceinline__ float lrelu(float x){ return x > 0.0f ? x : 0.2f*x; }
__device__ __forceinline__ float4 lrelu4(float4 v){
    return make_float4(lrelu(v.x), lrelu(v.y), lrelu(v.z), lrelu(v.w));
}
__device__ __forceinline__ void fma2(unsigned long long &d, unsigned long long a, unsigned long long b) {
    asm("fma.rn.f32x2 %0, %1, %2, %0;" : "+l"(d) : "l"(a), "l"(b));
}
__device__ __forceinline__ float2 unpack2(unsigned long long v) {
    float2 r; asm("mov.b64 {%0,%1}, %2;" : "=f"(r.x), "=f"(r.y) : "l"(v)); return r;
}
__device__ __forceinline__ unsigned long long pack2(float lo, float hi) {
    unsigned long long r; asm("mov.b64 %0, {%1,%2};" : "=l"(r) : "f"(lo), "f"(hi)); return r;
}

// ---------------- input 1x1 conv (3 -> 64): y -> g_full ----------------
__global__ void k_inconv(const float* __restrict__ x, const float* __restrict__ in_w,
                         const float* __restrict__ in_b)
{
    const int idx = blockIdx.x*256 + threadIdx.x;   // BB*NF*P0/4 = 2^21
    const int p4 = (idx & 4095) << 2;
    const int o  = (idx >> 12) & 63;
    const int b  = idx >> 18;
    const float w0 = in_w[o*3+0], w1 = in_w[o*3+1], w2 = in_w[o*3+2], bv = in_b[o];
    const float* xp = x + (size_t)(b*3)*P0 + p4;
    float4 a = *(const float4*)xp;
    float4 c = *(const float4*)(xp + P0);
    float4 d = *(const float4*)(xp + 2*P0);
    float4 r;
    r.x = bv + w0*a.x + w1*c.x + w2*d.x;
    r.y = bv + w0*a.y + w1*c.y + w2*d.y;
    r.z = bv + w0*a.z + w1*c.z + w2*d.z;
    r.w = bv + w0*a.w + w1*c.w + w2*d.w;
    *(float4*)&g_full[(size_t)(b*NF+o)*P0 + p4] = r;
}

// ---------------- transpose static resblock weights ----------------
__global__ void k_trw(const float* __restrict__ w0, const float* __restrict__ w1)
{
    const int i = blockIdx.x*256 + threadIdx.x;   // 8192
    if (i < 4096) { int k = i >> 6, o = i & 63; g_wRB[i] = w0[o*64 + k]; }
    else { int j = i - 4096; int k = j >> 6, o = j & 63; g_wRB[i] = w1[o*64 + k]; }
}

// ------- hypernet: dyn = inj_lat @ hyp_w + hyp_b (float4, batch-split grid) -----
__global__ void k_hyper(const float* __restrict__ inj, const float* __restrict__ hw,
                        const float* __restrict__ hb)
{
    __shared__ float s_inj[4*LATD];
    const int tid = threadIdx.x;  // 128
    const int b0 = blockIdx.y * 4;
    for (int e = tid; e < 4*LATD; e += 128) s_inj[e] = inj[b0*LATD + e];
    __syncthreads();
    const int j4 = (blockIdx.x*128 + tid) * 4;
    if (j4 >= PT) return;
    float4 acc[4];
    #pragma unroll
    for (int b = 0; b < 4; ++b) acc[b] = make_float4(0.f,0.f,0.f,0.f);
    for (int k = 0; k < LATD; ++k) {
        float4 w = *(const float4*)&hw[(size_t)k*PT + j4];
        #pragma unroll
        for (int b = 0; b < 4; ++b) {
            float s = s_inj[b*LATD+k];
            acc[b].x += s*w.x; acc[b].y += s*w.y;
            acc[b].z += s*w.z; acc[b].w += s*w.w;
        }
    }
    float4 bb = *(const float4*)&hb[j4];
    #pragma unroll
    for (int b = 0; b < 4; ++b) {
        float4 r = make_float4(acc[b].x+bb.x, acc[b].y+bb.y, acc[b].z+bb.z, acc[b].w+bb.w);
        *(float4*)&g_dyn[(size_t)(b0+b)*PT + j4] = r;
    }
}

// ---------------- transpose dyn params into GEMM-friendly layout ----------------
__global__ void k_tr()
{
    const int b = blockIdx.y;
    int i = blockIdx.x*256 + threadIdx.x;
    const float* d = g_dyn + (size_t)b*PT;
    if (i < FIN*FH) { int k = i/FH, o = i%FH; g_wAT[(size_t)b*FIN*FH + i] = d[o*FIN + k]; return; }
    i -= FIN*FH;
    if (i < FH*FH)  { int k = i/FH, o = i%FH; g_wMT[(size_t)b*FH*FH + i] = d[24704 + o*FH + k]; return; }
    i -= FH*FH;
    if (i < 320*NF) { int k = i/NF, o = i%NF;
        g_wCDT[(size_t)b*320*NF + i] = (k < FH) ? d[41216 + o*FH + k]
                                                : d[49472 + o*FIN + (k-FH)];
        return; }
    i -= 320*NF;
    if (i < FH) { g_bA[b*FH+i] = d[24576+i]; return; }
    i -= FH;
    if (i < FH) { g_bM[b*FH+i] = d[41088+i]; return; }
    i -= FH;
    if (i < NF) { g_bCD[b*NF+i] = d[49408+i] + d[61760+i]; return; }
}

// ------- sin_sobel derivatives only: g_out -> g_perc [2NF ch], 4 px/thread -------
__global__ void k_sobel4(int H, int lgH)
{
    const int P = H*H;
    const int idx = blockIdx.x*256 + threadIdx.x;
    if (idx >= BB*NF*(P>>2)) return;
    const int q  = idx & ((P>>2)-1);
    const int c  = (idx >> (2*lgH-2)) & 63;
    const int b  = idx >> (2*lgH+4);
    const int p4 = q << 2;
    const int y  = p4 >> lgH, x0 = p4 & (H-1);
    const float* src = g_out + (size_t)(b*NF+c)*P;

    float am[6], ac[6], ap[6];
    {
        float4 v = *(const float4*)&src[p4];
        ac[0] = (x0 > 0)     ? src[p4-1] : 0.f;
        ac[1] = v.x; ac[2] = v.y; ac[3] = v.z; ac[4] = v.w;
        ac[5] = (x0+4 < H)   ? src[p4+4] : 0.f;
    }
    if (y > 0) {
        int base = (y-1) << lgH;
        float4 v = *(const float4*)&src[base + x0];
        am[0] = (x0 > 0)   ? src[base+x0-1] : 0.f;
        am[1] = v.x; am[2] = v.y; am[3] = v.z; am[4] = v.w;
        am[5] = (x0+4 < H) ? src[base+x0+4] : 0.f;
    } else { am[0]=am[1]=am[2]=am[3]=am[4]=am[5]=0.f; }
    if (y < H-1) {
        int base = (y+1) << lgH;
        float4 v = *(const float4*)&src[base + x0];
        ap[0] = (x0 > 0)   ? src[base+x0-1] : 0.f;
        ap[1] = v.x; ap[2] = v.y; ap[3] = v.z; ap[4] = v.w;
        ap[5] = (x0+4 < H) ? src[base+x0+4] : 0.f;
    } else { ap[0]=ap[1]=ap[2]=ap[3]=ap[4]=ap[5]=0.f; }

    float sx[4], sy[4];
    #pragma unroll
    for (int i = 0; i < 4; ++i) {
        float m00 = am[i], m01 = am[i+1], m02 = am[i+2];
        float m10 = ac[i],               m12 = ac[i+2];
        float m20 = ap[i], m21 = ap[i+1], m22 = ap[i+2];
        sx[i] = (m00 - m02 + 2.f*(m10 - m12) + m20 - m22) * 0.125f;
        sy[i] = (m00 + 2.f*m01 + m02 - m20 - 2.f*m21 - m22) * 0.125f;
    }
    float* dst = g_perc + (size_t)b*(2*NF)*P;
    *(float4*)&dst[(size_t) c    *P + p4] = make_float4(sx[0],sx[1],sx[2],sx[3]);
    *(float4*)&dst[(size_t)(NF+c)*P + p4] = make_float4(sy[0],sy[1],sy[2],sy[3]);
}

// ---- fused input resblock: out = y + 0.1*( lrelu(lrelu(y)@w0+b0) @ w1 + b1 ) ----
// BM=256, BN=64, K=64 twice; h1 tile stays in smem between the two GEMMs.
__global__ void __launch_bounds__(256, 1) k_inres(
    const float* __restrict__ Y, const float* __restrict__ Wrb,
    const float* __restrict__ B0, const float* __restrict__ B1,
    float* __restrict__ OUT, float* __restrict__ EMB)
{
    constexpr int BM = 256, BN = 64, BK = 32, TMC = 32;
    extern __shared__ float smem[];
    float (*As)[BK][BM] = (float(*)[BK][BM])smem;
    float (*Ws)[BK][BN] = (float(*)[BK][BN])(smem + 2*BK*BM);

    const int b  = blockIdx.y;
    const int m0 = blockIdx.x * BM;
    const float* Yb = Y + (size_t)b*NF*P0;
    const int tid = threadIdx.x;
    const int tm = tid % TMC, tn = tid / TMC;

    // stage lrelu(Y) (K=64 -> both buffers) and W0
    #pragma unroll
    for (int l = 0; l < 16; ++l) {
        int f = tid + l*256;
        int kk = f >> 6;
        int mv = (f & 63) << 2;
        float4 v = *(const float4*)(Yb + (size_t)kk*P0 + m0 + mv);
        *(float4*)&As[kk>>5][kk&31][mv] = lrelu4(v);
    }
    #pragma unroll
    for (int l = 0; l < 4; ++l) {
        int f = tid + l*256;
        int kk = f >> 4;
        int nv = (f & 15) << 2;
        *(float4*)&Ws[kk>>5][kk&31][nv] = *(const float4*)(Wrb + kk*BN + nv);
    }
    __syncthreads();

    unsigned long long acc[2][2][4][2];
    #pragma unroll
    for (int af=0; af<2; ++af)
        #pragma unroll
        for (int wf=0; wf<2; ++wf)
            #pragma unroll
            for (int j=0;j<4;++j){ acc[af][wf][j][0]=0ULL; acc[af][wf][j][1]=0ULL; }

    #pragma unroll
    for (int t = 0; t < 2; ++t)
        #pragma unroll
        for (int kc = 0; kc < BK; ++kc) {
            ulonglong2 aA = *(const ulonglong2*)&As[t][kc][tm*4];
            ulonglong2 aB = *(const ulonglong2*)&As[t][kc][128 + tm*4];
            float4 wa = *(const float4*)&Ws[t][kc][tn*4];
            float4 wb = *(const float4*)&Ws[t][kc][32 + tn*4];
            unsigned long long wd[2][4];
            wd[0][0]=pack2(wa.x,wa.x); wd[0][1]=pack2(wa.y,wa.y);
            wd[0][2]=pack2(wa.z,wa.z); wd[0][3]=pack2(wa.w,wa.w);
            wd[1][0]=pack2(wb.x,wb.x); wd[1][1]=pack2(wb.y,wb.y);
            wd[1][2]=pack2(wb.z,wb.z); wd[1][3]=pack2(wb.w,wb.w);
            #pragma unroll
            for (int wf = 0; wf < 2; ++wf)
                #pragma unroll
                for (int j = 0; j < 4; ++j) {
                    fma2(acc[0][wf][j][0], wd[wf][j], aA.x);
                    fma2(acc[0][wf][j][1], wd[wf][j], aA.y);
                    fma2(acc[1][wf][j][0], wd[wf][j], aB.x);
                    fma2(acc[1][wf][j][1], wd[wf][j], aB.y);
                }
        }
    __syncthreads();   // all As/Ws reads done

    // h1 = lrelu(acc + b0) -> As (k = n layout); stage W1
    #pragma unroll
    for (int wf = 0; wf < 2; ++wf)
        #pragma unroll
        for (int j = 0; j < 4; ++j) {
            const int n = wf*32 + tn*4 + j;
            const float bv = B0[n];
            #pragma unroll
            for (int af = 0; af < 2; ++af) {
                float2 p0 = unpack2(acc[af][wf][j][0]);
                float2 p1 = unpack2(acc[af][wf][j][1]);
                *(float4*)&As[n>>5][n&31][af*128 + tm*4] =
                    make_float4(lrelu(p0.x+bv), lrelu(p0.y+bv),
                                lrelu(p1.x+bv), lrelu(p1.y+bv));
                acc[af][wf][j][0] = 0ULL; acc[af][wf][j][1] = 0ULL;
            }
        }
    #pragma unroll
    for (int l = 0; l < 4; ++l) {
        int f = tid + l*256;
        int kk = f >> 4;
        int nv = (f & 15) << 2;
        *(float4*)&Ws[kk>>5][kk&31][nv] = *(const float4*)(Wrb + NF*2*NF/2 + kk*BN + nv);
    }
    __syncthreads();

    #pragma unroll
    for (int t = 0; t < 2; ++t)
        #pragma unroll
        for (int kc = 0; kc < BK; ++kc) {
            ulonglong2 aA = *(const ulonglong2*)&As[t][kc][tm*4];
            ulonglong2 aB = *(const ulonglong2*)&As[t][kc][128 + tm*4];
            float4 wa = *(const float4*)&Ws[t][kc][tn*4];
            float4 wb = *(const float4*)&Ws[t][kc][32 + tn*4];
            unsigned long long wd[2][4];
            wd[0][0]=pack2(wa.x,wa.x); wd[0][1]=pack2(wa.y,wa.y);
            wd[0][2]=pack2(wa.z,wa.z); wd[0][3]=pack2(wa.w,wa.w);
            wd[1][0]=pack2(wb.x,wb.x); wd[1][1]=pack2(wb.y,wb.y);
            wd[1][2]=pack2(wb.z,wb.z); wd[1][3]=pack2(wb.w,wb.w);
            #pragma unroll
            for (int wf = 0; wf < 2; ++wf)
                #pragma unroll
                for (int j = 0; j < 4; ++j) {
                    fma2(acc[0][wf][j][0], wd[wf][j], aA.x);
                    fma2(acc[0][wf][j][1], wd[wf][j], aA.y);
                    fma2(acc[1][wf][j][0], wd[wf][j], aB.x);
                    fma2(acc[1][wf][j][1], wd[wf][j], aB.y);
                }
        }

    // epilogue: out = y + 0.1*(acc + b1), dual-store OUT/EMB
    #pragma unroll
    for (int af = 0; af < 2; ++af) {
        const int m = m0 + af*128 + tm*4;
        #pragma unroll
        for (int wf = 0; wf < 2; ++wf) {
            #pragma unroll
            for (int j = 0; j < 4; ++j) {
                const int n = wf*32 + tn*4 + j;
                const float bv = B1[n];
                float2 p0 = unpack2(acc[af][wf][j][0]);
                float2 p1 = unpack2(acc[af][wf][j][1]);
                float4 y4 = *(const float4*)(Yb + (size_t)n*P0 + m);
                float4 v;
                v.x = y4.x + 0.1f*(p0.x+bv);
                v.y = y4.y + 0.1f*(p0.y+bv);
                v.z = y4.z + 0.1f*(p1.x+bv);
                v.w = y4.w + 0.1f*(p1.y+bv);
                const size_t off = (size_t)(b*NF+n)*P0 + m;
                *(float4*)&OUT[off] = v;
                *(float4*)&EMB[off] = v;
            }
        }
    }
}

// ---------------- SGEMM: C[n][p] = sum_k A[k][p] * Wt[k][n] (+epilogue) ----------
// 256 threads, per-thread MT x 8N via fma.rn.f32x2. Up to 3 A-segments.
// EPI 0: C = lrelu(v+bias)
// EPI 1: C = O + clip(*leak)*(v+bias)
template<int BM, int BN, int EPI, int MT>
__global__ void __launch_bounds__(256, 1) k_gemm(
    const float* __restrict__ A1, int K1, long long sA1,
    const float* __restrict__ A2, int K2, long long sA2,
    const float* __restrict__ A3, int K3, long long sA3,
    const float* __restrict__ Wt, int ldw, long long sW,
    const float* __restrict__ bias, int sBias,
    float* __restrict__ C, long long sC,
    const float* __restrict__ O, const float* __restrict__ leak_ptr,
    int P, int tilesM)
{
    constexpr int BK  = 32;
    constexpr int TMC = BM/MT;
    constexpr int NA  = BK*BM/1024;
    constexpr int NW  = (BK*BN >= 1024) ? BK*BN/1024 : 1;

    extern __shared__ float smem[];
    float (*As)[BK][BM] = (float(*)[BK][BM])smem;
    float (*Ws)[BK][BN] = (float(*)[BK][BN])(smem + 2*BK*BM);

    const int b  = blockIdx.y;
    const int m0 = (blockIdx.x % tilesM) * BM;
    const int n0 = (blockIdx.x / tilesM) * BN;
    A1 += (size_t)b * sA1;
    if (A2) A2 += (size_t)b * sA2;
    if (A3) A3 += (size_t)b * sA3;
    Wt   += (size_t)b * sW;
    bias += (size_t)b * sBias;

    const int tid = threadIdx.x;
    const int tm = tid % TMC;
    const int tn = tid / TMC;

    constexpr int AF = MT/4;
    unsigned long long acc[AF][2][4][2];
    #pragma unroll
    for (int af = 0; af < AF; ++af)
        #pragma unroll
        for (int wf = 0; wf < 2; ++wf)
            #pragma unroll
            for (int j = 0; j < 4; ++j) { acc[af][wf][j][0] = 0ULL; acc[af][wf][j][1] = 0ULL; }

    const int K12 = K1 + K2;
    const int K = K12 + K3;
    const int T = K / BK;

    float4 pa[NA], pw[NW];
    auto prefetch = [&](int k0) {
        #pragma unroll
        for (int l = 0; l < NA; ++l) {
            int f  = tid + l*256;
            int kc = f / (BM/4);
            int mv = (f % (BM/4)) * 4;
            int kk = k0 + kc;
            int m  = m0 + mv;
            const float* src;
            if (kk < K1)      src = A1 + (size_t)kk*P;
            else if (kk < K12) src = A2 + (size_t)(kk-K1)*P;
            else               src = A3 + (size_t)(kk-K12)*P;
            pa[l] = (m < P) ? *(const float4*)(src + m) : make_float4(0.f,0.f,0.f,0.f);
        }
        #pragma unroll
        for (int l = 0; l < NW; ++l) {
            int f  = tid + l*256;
            int kc = f / (BN/4);
            int nv = (f % (BN/4)) * 4;
            pw[l] = *(const float4*)(Wt + (size_t)(k0+kc)*ldw + n0 + nv);
        }
    };
    auto store_tile = [&](int nb) {
        #pragma unroll
        for (int l = 0; l < NA; ++l) {
            int f  = tid + l*256;
            int kc = f / (BM/4);
            int mv = (f % (BM/4)) * 4;
            *(float4*)&As[nb][kc][mv] = pa[l];
        }
        #pragma unroll
        for (int l = 0; l < NW; ++l) {
            int f  = tid + l*256;
            int kc = f / (BN/4);
            int nv = (f % (BN/4)) * 4;
            *(float4*)&Ws[nb][kc][nv] = pw[l];
        }
    };

    prefetch(0);
    store_tile(0);
    __syncthreads();

    for (int t = 0; t < T; ++t) {
        const int buf = t & 1;
        if (t + 1 < T) prefetch((t + 1) * BK);
        #pragma unroll
        for (int kc = 0; kc < BK; ++kc) {
            ulonglong2 aA = *(const ulonglong2*)&As[buf][kc][tm*4];
            ulonglong2 aB;
            if (MT == 8) aB = *(const ulonglong2*)&As[buf][kc][BM/2 + tm*4];
            float4 wa = *(const float4*)&Ws[buf][kc][tn*4];
            float4 wb = *(const float4*)&Ws[buf][kc][BN/2 + tn*4];
            unsigned long long wd[2][4];
            wd[0][0] = pack2(wa.x, wa.x); wd[0][1] = pack2(wa.y, wa.y);
            wd[0][2] = pack2(wa.z, wa.z); wd[0][3] = pack2(wa.w, wa.w);
            wd[1][0] = pack2(wb.x, wb.x); wd[1][1] = pack2(wb.y, wb.y);
            wd[1][2] = pack2(wb.z, wb.z); wd[1][3] = pack2(wb.w, wb.w);
            #pragma unroll
            for (int wf = 0; wf < 2; ++wf)
                #pragma unroll
                for (int j = 0; j < 4; ++j) {
                    fma2(acc[0][wf][j][0], wd[wf][j], aA.x);
                    fma2(acc[0][wf][j][1], wd[wf][j], aA.y);
                    if (MT == 8) {
                        fma2(acc[AF-1][wf][j][0], wd[wf][j], aB.x);
                        fma2(acc[AF-1][wf][j][1], wd[wf][j], aB.y);
                    }
                }
        }
        if (t + 1 < T) store_tile(buf ^ 1);
        __syncthreads();
    }

    float lk = 0.1f;
    if (EPI == 1) { lk = *leak_ptr; lk = fminf(fmaxf(lk, 0.001f), 1000.f); }
    #pragma unroll
    for (int af = 0; af < AF; ++af) {
        const int m = m0 + (af ? BM/2 : 0) + tm*4;
        if (m >= P) continue;
        #pragma unroll
        for (int wf = 0; wf < 2; ++wf) {
            #pragma unroll
            for (int j = 0; j < 4; ++j) {
                const int n = n0 + (wf ? BN/2 : 0) + tn*4 + j;
                const float bv = bias[n];
                float2 p0 = unpack2(acc[af][wf][j][0]);
                float2 p1 = unpack2(acc[af][wf][j][1]);
                float4 v = make_float4(p0.x+bv, p0.y+bv, p1.x+bv, p1.y+bv);
                const size_t off = (size_t)b*sC + (size_t)n*P + m;
                if (EPI == 0) {
                    *(float4*)&C[off] = lrelu4(v);
                } else {
                    float4 o = *(const float4*)&O[off];
                    v.x = o.x + lk*v.x; v.y = o.y + lk*v.y;
                    v.z = o.z + lk*v.z; v.w = o.w + lk*v.w;
                    *(float4*)&C[off] = v;
                }
            }
        }
    }
}

// ---------------- gauss 3x3 (zero pad) + 2x2 mean, writes g_out + emb ----------------
__global__ void k_down(int H, int lgH, float* __restrict__ emb)
{
    const int Hn = H >> 1, Pn = Hn*Hn;
    const int lgHn = lgH - 1;
    const int idx = blockIdx.x*256 + threadIdx.x;
    if (idx >= BB*NF*Pn) return;
    const int p = idx & (Pn-1);
    const int c = (idx >> (2*lgHn)) & (NF-1);
    const int b = idx >> (2*lgHn + 6);
    const int oy = p >> lgHn, ox = p & (Hn-1);
    const float* src = g_full + (size_t)(b*NF+c)*H*H;
    const float G0 = 0.27406861906119695f;
    const float G1 = 0.72593138093880305f;
    const float u4[4] = {G0, G1, G1, G0};
    float acc = 0.f;
    #pragma unroll
    for (int r = 0; r < 4; ++r) {
        int yy = 2*oy + r - 1;
        if (yy < 0 || yy >= H) continue;
        float rowacc = 0.f;
        #pragma unroll
        for (int cc = 0; cc < 4; ++cc) {
            int xx = 2*ox + cc - 1;
            if (xx < 0 || xx >= H) continue;
            rowacc += u4[cc]*src[(yy<<lgH)+xx];
        }
        acc += u4[r]*rowacc;
    }
    acc *= 0.25f;
    const size_t o = (size_t)(b*NF+c)*Pn + p;
    g_out[o] = acc;
    emb[o]   = acc;
}

// ---------------- tail res_block at 2x2 + spatial mean -> g_hvec ----------------
__global__ void k_tail(const float* __restrict__ w0, const float* __restrict__ b0,
                       const float* __restrict__ w1, const float* __restrict__ b1)
{
    __shared__ float s_w0[NF*NF], s_w1[NF*NF], s_a[NF*4];
    const int o = threadIdx.x, b = blockIdx.x;
    for (int e = o; e < NF*NF; e += 64) {
        int r = e >> 6, i = e & 63;
        s_w0[(r<<6) | ((i + r) & 63)] = w0[e];
        s_w1[(r<<6) | ((i + r) & 63)] = w1[e];
    }
    const float bb0 = b0[o], bb1 = b1[o];
    __syncthreads();
    float v[4];
    #pragma unroll
    for (int py = 0; py < 4; ++py) v[py] = g_out[(size_t)(b*NF+o)*4 + py];
    *(float4*)&s_a[o*4] = make_float4(lrelu(v[0]),lrelu(v[1]),lrelu(v[2]),lrelu(v[3]));
    __syncthreads();
    float t[4] = {bb0,bb0,bb0,bb0};
    #pragma unroll
    for (int i = 0; i < NF; ++i) {
        float w = s_w0[(o<<6) | ((i + o) & 63)];
        float4 a = *(const float4*)&s_a[i*4];
        t[0] += w*a.x; t[1] += w*a.y; t[2] += w*a.z; t[3] += w*a.w;
    }
    __syncthreads();
    *(float4*)&s_a[o*4] = make_float4(lrelu(t[0]),lrelu(t[1]),lrelu(t[2]),lrelu(t[3]));
    __syncthreads();
    float u[4] = {bb1,bb1,bb1,bb1};
    #pragma unroll
    for (int i = 0; i < NF; ++i) {
        float w = s_w1[(o<<6) | ((i + o) & 63)];
        float4 a = *(const float4*)&s_a[i*4];
        u[0] += w*a.x; u[1] += w*a.y; u[2] += w*a.z; u[3] += w*a.w;
    }
    float m = 0.25f*((v[0]+0.1f*u[0]) + (v[1]+0.1f*u[1]) + (v[2]+0.1f*u[2]) + (v[3]+0.1f*u[3]));
    g_hvec[b*NF+o] = m;
}

// ---------------- latent head ----------------
__global__ void __launch_bounds__(512) k_head(
    const float* __restrict__ l1_sw, const float* __restrict__ l1_sb,
    const float* __restrict__ l1_w1, const float* __restrict__ l1_b1,
    const float* __restrict__ l1_w2, const float* __restrict__ l1_b2,
    const float* __restrict__ l2_w1, const float* __restrict__ l2_b1,
    const float* __restrict__ l2_w2, const float* __restrict__ l2_b2,
    const float* __restrict__ lo_w,  const float* __restrict__ lo_b,
    float* __restrict__ lat)
{
    __shared__ float s_h[NF], s_ha[NF];
    __shared__ float s_t[2*LATD];
    __shared__ float s_u[LATD];
    __shared__ float s_hh[LATD];
    const int j = threadIdx.x, b = blockIdx.x;
    if (j < NF) { float h = g_hvec[b*NF+j]; s_h[j] = h; s_ha[j] = lrelu(h); }
    __syncthreads();
    float xs = l1_sb[j];
    for (int i = 0; i < NF; ++i) xs += s_h[i]*l1_sw[i*LATD + j];
    float t0 = l1_b1[j], t1 = l1_b1[j+LATD];
    for (int i = 0; i < NF; ++i) {
        float a = s_ha[i];
        t0 += a*l1_w1[i*2*LATD + j];
        t1 += a*l1_w1[i*2*LATD + j + LATD];
    }
    s_t[j] = lrelu(t0); s_t[j+LATD] = lrelu(t1);
    __syncthreads();
    float v = l1_b2[j];
    for (int i = 0; i < 2*LATD; ++i) v += s_t[i]*l1_w2[(size_t)i*LATD + j];
    float hh = xs + 0.1f*v;
    s_hh[j] = hh; s_u[j] = lrelu(hh);
    __syncthreads();
    float t2 = l2_b1[j];
    for (int i = 0; i < LATD; ++i) t2 += s_u[i]*l2_w1[(size_t)i*LATD + j];
    __syncthreads();
    s_u[j] = lrelu(t2);
    __syncthreads();
    float v2 = l2_b2[j];
    for (int i = 0; i < LATD; ++i) v2 += s_u[i]*l2_w2[(size_t)i*LATD + j];
    float g = s_hh[j] + 0.1f*v2;
    s_t[j] = g;
    __syncthreads();
    float outv = lo_b[j];
    for (int i = 0; i < LATD; ++i) outv += s_t[i]*lo_w[(size_t)i*LATD + j];
    lat[b*LATD + j] = outv;
}

// ---------------- host launcher ----------------
extern "C" void kernel_launch(void* const* d_in, const int* in_sizes, int n_in,
                              void* d_out, int out_size)
{
    const float* x        = (const float*)d_in[0];
    const float* inj      = (const float*)d_in[1];
    const float* leak     = (const float*)d_in[2];
    const float* in_w     = (const float*)d_in[3];
    const float* in_b     = (const float*)d_in[4];
    const float* inrb_w0  = (const float*)d_in[5];
    const float* inrb_b0  = (const float*)d_in[6];
    const float* inrb_w1  = (const float*)d_in[7];
    const float* inrb_b1  = (const float*)d_in[8];
    const float* hyp_w    = (const float*)d_in[9];
    const float* hyp_b    = (const float*)d_in[10];
    const float* outrb_w0 = (const float*)d_in[11];
    const float* outrb_b0 = (const float*)d_in[12];
    const float* outrb_w1 = (const float*)d_in[13];
    const float* outrb_b1 = (const float*)d_in[14];
    const float* l1_sw    = (const float*)d_in[15];
    const float* l1_sb    = (const float*)d_in[16];
    const float* l1_w1    = (const float*)d_in[17];
    const float* l1_b1    = (const float*)d_in[18];
    const float* l1_w2    = (const float*)d_in[19];
    const float* l1_b2    = (const float*)d_in[20];
    const float* l2_w1    = (const float*)d_in[21];
    const float* l2_b1    = (const float*)d_in[22];
    const float* l2_w2    = (const float*)d_in[23];
    const float* l2_b2    = (const float*)d_in[24];
    const float* lo_w     = (const float*)d_in[25];
    const float* lo_b     = (const float*)d_in[26];
    float* out = (float*)d_out;

    float *p_perc, *p_h1, *p_h2, *p_full, *p_out, *p_wAT, *p_wMT, *p_wCDT, *p_bA, *p_bM, *p_bCD, *p_wRB;
    cudaGetSymbolAddress((void**)&p_perc, g_perc);
    cudaGetSymbolAddress((void**)&p_h1,   g_h1);
    cudaGetSymbolAddress((void**)&p_h2,   g_h2);
    cudaGetSymbolAddress((void**)&p_full, g_full);
    cudaGetSymbolAddress((void**)&p_out,  g_out);
    cudaGetSymbolAddress((void**)&p_wAT,  g_wAT);
    cudaGetSymbolAddress((void**)&p_wMT,  g_wMT);
    cudaGetSymbolAddress((void**)&p_wCDT, g_wCDT);
    cudaGetSymbolAddress((void**)&p_bA,   g_bA);
    cudaGetSymbolAddress((void**)&p_bM,   g_bM);
    cudaGetSymbolAddress((void**)&p_bCD,  g_bCD);
    cudaGetSymbolAddress((void**)&p_wRB,  g_wRB);

    // dynamic smem sizes: (2*BK*BM + 2*BK*BN) * 4 bytes, BK=32
    const int SM_128_128 = (2*32*128 + 2*32*128) * 4;   // 64 KB
    const int SM_256_64  = (2*32*256 + 2*32*64)  * 4;   // 80 KB
    const int SM_128_64  = (2*32*128 + 2*32*64)  * 4;   // 48 KB
    cudaFuncSetAttribute(k_inres,                  cudaFuncAttributeMaxDynamicSharedMemorySize, SM_256_64);
    cudaFuncSetAttribute(k_gemm<256,64,1,8>,  cudaFuncAttributeMaxDynamicSharedMemorySize, SM_256_64);
    cudaFuncSetAttribute(k_gemm<128,128,0,8>, cudaFuncAttributeMaxDynamicSharedMemorySize, SM_128_128);
    cudaFuncSetAttribute(k_gemm<128,64,0,4>,  cudaFuncAttributeMaxDynamicSharedMemorySize, SM_128_64);
    cudaFuncSetAttribute(k_gemm<128,64,1,4>,  cudaFuncAttributeMaxDynamicSharedMemorySize, SM_128_64);

    float* emb0 = out + (size_t)BB*LATD;   // lat occupies [0, 4096)

    k_inconv<<<8192, 256>>>(x, in_w, in_b);
    k_trw<<<32, 256>>>(inrb_w0, inrb_w1);
    k_hyper<<<dim3((PT/4 + 127)/128, 2), 128>>>(inj, hyp_w, hyp_b);
    // fused input resblock -> g_out and emb0
    k_inres<<<dim3(P0/256, BB), 256, SM_256_64>>>(
        p_full, p_wRB, inrb_b0, inrb_b1, p_out, emb0);
    k_tr<<<dim3((61760 + 255)/256, BB), 256>>>();

    size_t off = (size_t)BB*LATD + (size_t)BB*NF*P0;
    int H = 128, lgH = 7;
    for (int it = 0; it < 6; ++it) {
        int P = H*H;
        k_sobel4<<<(BB*NF*(P/4) + 255)/256, 256>>>(H, lgH);
        if (P > 1024) {
            int tM = (P + 127)/128;
            k_gemm<128,128,0,8><<<dim3(tM, BB), 256, SM_128_128>>>(
                p_out, NF, (long long)NF*P, p_perc, 2*NF, (long long)2*NF*P,
                nullptr, 0, 0,
                p_wAT, FH, (long long)FIN*FH, p_bA, FH,
                p_h1, (long long)FH*P, nullptr, nullptr, P, tM);
            k_gemm<128,128,0,8><<<dim3(tM, BB), 256, SM_128_128>>>(
                p_h1, FH, (long long)FH*P, nullptr, 0, 0,
                nullptr, 0, 0,
                p_wMT, FH, (long long)FH*FH, p_bM, FH,
                p_h2, (long long)FH*P, nullptr, nullptr, P, tM);
            int tM2 = (P + 255)/256;
            k_gemm<256,64,1,8><<<dim3(tM2, BB), 256, SM_256_64>>>(
                p_h2, FH, (long long)FH*P, p_out, NF, (long long)NF*P,
                p_perc, 2*NF, (long long)2*NF*P,
                p_wCDT, NF, (long long)320*NF, p_bCD, NF,
                p_full, (long long)NF*P, p_out, leak, P, tM2);
        } else {
            int tM = (P + 127)/128;
            k_gemm<128,64,0,4><<<dim3(tM*2, BB), 256, SM_128_64>>>(
                p_out, NF, (long long)NF*P, p_perc, 2*NF, (long long)2*NF*P,
                nullptr, 0, 0,
                p_wAT, FH, (long long)FIN*FH, p_bA, FH,
                p_h1, (long long)FH*P, nullptr, nullptr, P, tM);
            k_gemm<128,64,0,4><<<dim3(tM*2, BB), 256, SM_128_64>>>(
                p_h1, FH, (long long)FH*P, nullptr, 0, 0,
                nullptr, 0, 0,
                p_wMT, FH, (long long)FH*FH, p_bM, FH,
                p_h2, (long long)FH*P, nullptr, nullptr, P, tM);
            k_gemm<128,64,1,4><<<dim3(tM, BB), 256, SM_128_64>>>(
                p_h2, FH, (long long)FH*P, p_out, NF, (long long)NF*P,
                p_perc, 2*NF, (long long)2*NF*P,
                p_wCDT, NF, (long long)320*NF, p_bCD, NF,
                p_full, (long long)NF*P, p_out, leak, P, tM);
        }
        int Hn = H/2, Pn = Hn*Hn;
        k_down<<<(BB*NF*Pn + 255)/256, 256>>>(H, lgH, out + off);
        off += (size_t)BB*NF*Pn;
        H = Hn; lgH -= 1;
    }
    k_tail<<<BB, 64>>>(outrb_w0, outrb_b0, outrb_w1, outrb_b1);
    k_head<<<BB, 512>>>(l1_sw, l1_sb, l1_w1, l1_b1, l1_w2, l1_b2,
                        l2_w1, l2_b1, l2_w2, l2_b2, lo_w, lo_b, out);
}